// round 6
// baseline (speedup 1.0000x reference)
#include <cuda_runtime.h>
#include <math.h>

#define NN 40000
#define EE 640000
#define GG 32
#define HH 128
#define LL 4
#define OO 100

// ---------------- device scratch ----------------
__device__ float g_hA[NN * HH];
__device__ float g_hB[NN * HH];
__device__ float g_eh[EE * HH];       // edge projection, CSR-permuted order
__device__ float g_q [NN * HH];
__device__ float g_k [NN * HH];
__device__ float g_v [NN * HH];
__device__ float g_s [NN * HH];
__device__ float g_u  [NN * 512];     // per-node per-head logit vectors in e_h space
__device__ float g_agg[NN * 512];     // alpha-weighted e_h accumulation (normalized)
__device__ float g_tmpv[NN * HH];     // v-part + skip (pre-LN)
__device__ float g_Wt[LL * HH * HH];  // We transposed per layer
__device__ int   g_hist[NN];
__device__ int   g_rowstart[NN + 1];
__device__ int   g_cursor[NN];
__device__ int   g_edgepos[EE];
__device__ int   g_csrsrc[EE];
__device__ float g_pool[GG * HH];
__device__ float g_pcnt[GG];

// ---------------- CSR construction ----------------
__global__ void k_zero()
{
    int i = blockIdx.x * blockDim.x + threadIdx.x;
    if (i < NN) g_hist[i] = 0;
    if (i < GG * HH) g_pool[i] = 0.f;
    if (i < GG) g_pcnt[i] = 0.f;
}

__global__ void k_hist(const int* __restrict__ ei)
{
    int e = blockIdx.x * blockDim.x + threadIdx.x;
    if (e < EE) atomicAdd(&g_hist[ei[EE + e]], 1);
}

__global__ void k_scan()
{
    const int T = 1024, CH = 40;
    __shared__ int sh[T];
    int t = threadIdx.x;
    int base = t * CH;
    int loc[CH];
    int run = 0;
#pragma unroll
    for (int i = 0; i < CH; i++) {
        int idx = base + i;
        int vv = (idx < NN) ? g_hist[idx] : 0;
        loc[i] = run;
        run += vv;
    }
    sh[t] = run;
    __syncthreads();
    for (int off = 1; off < T; off <<= 1) {
        int vv = (t >= off) ? sh[t - off] : 0;
        __syncthreads();
        sh[t] += vv;
        __syncthreads();
    }
    int offset = (t > 0) ? sh[t - 1] : 0;
#pragma unroll
    for (int i = 0; i < CH; i++) {
        int idx = base + i;
        if (idx < NN) {
            int p = offset + loc[i];
            g_rowstart[idx] = p;
            g_cursor[idx]   = p;
        }
    }
    if (t == T - 1) g_rowstart[NN] = sh[T - 1];
}

__global__ void k_scatter(const int* __restrict__ ei)
{
    int e = blockIdx.x * blockDim.x + threadIdx.x;
    if (e < EE) {
        int dst = ei[EE + e];
        int pos = atomicAdd(&g_cursor[dst], 1);
        g_edgepos[e] = pos;
        g_csrsrc[pos] = ei[e];
    }
}

// ---------------- input projections ----------------
__global__ void k_nodeproj(const float* __restrict__ x,
                           const float* __restrict__ w,
                           const float* __restrict__ b)
{
    int t = blockIdx.x * blockDim.x + threadIdx.x;
    if (t >= NN * HH) return;
    int n = t >> 7, c = t & 127;
    const float* xr = x + n * 4;
    float acc = b[c];
    acc += xr[0] * w[c] + xr[1] * w[128 + c] + xr[2] * w[256 + c] + xr[3] * w[384 + c];
    g_hA[t] = acc;
}

__global__ void k_edgeproj(const float* __restrict__ ea,
                           const float* __restrict__ w,
                           const float* __restrict__ b)
{
    int t = blockIdx.x * blockDim.x + threadIdx.x;
    if (t >= EE * HH) return;
    int e = t >> 7, c = t & 127;
    const float* ar = ea + e * 5;
    float acc = b[c];
#pragma unroll
    for (int j = 0; j < 5; j++) acc += ar[j] * w[j * 128 + c];
    int pos = g_edgepos[e];
    g_eh[pos * HH + c] = acc;
}

__global__ void k_trWe(const float* __restrict__ We)
{
    int t = blockIdx.x * blockDim.x + threadIdx.x;
    if (t >= LL * HH * HH) return;
    int l = t >> 14;
    int rem = t & 16383;
    int c = rem >> 7, j = rem & 127;
    g_Wt[t] = We[l * HH * HH + j * HH + c];
}

// ---------------- fused 4-matrix GEMM (R3-proven) ----------------
#define BM 64
#define BK 16

__global__ void gemm4(const float* __restrict__ A,
                      const float* __restrict__ B0, const float* __restrict__ B1,
                      const float* __restrict__ B2, const float* __restrict__ B3,
                      const float* __restrict__ c0, const float* __restrict__ c1,
                      const float* __restrict__ c2, const float* __restrict__ c3,
                      float* __restrict__ C0, float* __restrict__ C1,
                      float* __restrict__ C2, float* __restrict__ C3)
{
    const float* B    = (blockIdx.y == 0) ? B0 : (blockIdx.y == 1) ? B1 : (blockIdx.y == 2) ? B2 : B3;
    const float* bias = (blockIdx.y == 0) ? c0 : (blockIdx.y == 1) ? c1 : (blockIdx.y == 2) ? c2 : c3;
    float* C          = (blockIdx.y == 0) ? C0 : (blockIdx.y == 1) ? C1 : (blockIdx.y == 2) ? C2 : C3;

    __shared__ float As[BK][BM + 4];
    __shared__ float Bs[BK][128];
    int tid  = threadIdx.x;
    int tcol = tid & 15;
    int trow = tid >> 4;
    int block_m = blockIdx.x * BM;

    float acc[8][8];
#pragma unroll
    for (int i = 0; i < 8; i++)
#pragma unroll
        for (int j = 0; j < 8; j++) acc[i][j] = 0.f;

    for (int k0 = 0; k0 < 128; k0 += BK) {
#pragma unroll
        for (int it = 0; it < 2; it++) {
            int f = tid + it * 128;
            int row = f >> 2;
            int kq  = f & 3;
            float4 a = *(const float4*)&A[(size_t)(block_m + row) * 128 + k0 + kq * 4];
            As[kq * 4 + 0][row] = a.x;
            As[kq * 4 + 1][row] = a.y;
            As[kq * 4 + 2][row] = a.z;
            As[kq * 4 + 3][row] = a.w;
        }
#pragma unroll
        for (int it = 0; it < 4; it++) {
            int f = tid + it * 128;
            int krow = f >> 5;
            int nq   = f & 31;
            *(float4*)&Bs[krow][nq * 4] = *(const float4*)&B[(k0 + krow) * 128 + nq * 4];
        }
        __syncthreads();
#pragma unroll
        for (int k = 0; k < BK; k++) {
            float a[8], b[8];
            *(float4*)&a[0] = *(float4*)&As[k][trow * 4];
            *(float4*)&a[4] = *(float4*)&As[k][32 + trow * 4];
            *(float4*)&b[0] = *(float4*)&Bs[k][tcol * 4];
            *(float4*)&b[4] = *(float4*)&Bs[k][64 + tcol * 4];
#pragma unroll
            for (int i = 0; i < 8; i++)
#pragma unroll
                for (int j = 0; j < 8; j++)
                    acc[i][j] += a[i] * b[j];
        }
        __syncthreads();
    }

    float4 bLo = *(const float4*)&bias[tcol * 4];
    float4 bHi = *(const float4*)&bias[64 + tcol * 4];
#pragma unroll
    for (int i = 0; i < 8; i++) {
        int row = block_m + ((i < 4) ? (trow * 4 + i) : (32 + trow * 4 + i - 4));
        float4 lo, hi;
        lo.x = acc[i][0] + bLo.x; lo.y = acc[i][1] + bLo.y;
        lo.z = acc[i][2] + bLo.z; lo.w = acc[i][3] + bLo.w;
        hi.x = acc[i][4] + bHi.x; hi.y = acc[i][5] + bHi.y;
        hi.z = acc[i][6] + bHi.z; hi.w = acc[i][7] + bHi.w;
        *(float4*)&C[(size_t)row * 128 + tcol * 4]      = lo;
        *(float4*)&C[(size_t)row * 128 + 64 + tcol * 4] = hi;
    }
}

// ---------------- u kernel (R3-proven) ----------------
__global__ void k_uproj(const float* __restrict__ q, const float* __restrict__ We)
{
    __shared__ float sW[128][33];
    __shared__ float sQ[32][32];
    const float scale = 0.17677669529663687f;
    int tid  = threadIdx.x;
    int warp = tid >> 5;
    int lane = tid & 31;
    int base = blockIdx.x * 32;

    for (int h = 0; h < 4; h++) {
        for (int idx = tid; idx < 128 * 8; idx += 256) {
            int j = idx >> 3, c4 = idx & 7;
            float4 w4 = *(const float4*)&We[j * 128 + h * 32 + c4 * 4];
            sW[j][c4 * 4 + 0] = w4.x;
            sW[j][c4 * 4 + 1] = w4.y;
            sW[j][c4 * 4 + 2] = w4.z;
            sW[j][c4 * 4 + 3] = w4.w;
        }
        for (int idx = tid; idx < 32 * 8; idx += 256) {
            int n = idx >> 3, c4 = idx & 7;
            float4 q4 = *(const float4*)&q[(size_t)(base + n) * 128 + h * 32 + c4 * 4];
            sQ[n][c4 * 4 + 0] = q4.x;
            sQ[n][c4 * 4 + 1] = q4.y;
            sQ[n][c4 * 4 + 2] = q4.z;
            sQ[n][c4 * 4 + 3] = q4.w;
        }
        __syncthreads();

        float acc[4][4];
#pragma unroll
        for (int i = 0; i < 4; i++)
#pragma unroll
            for (int jj = 0; jj < 4; jj++) acc[i][jj] = 0.f;

        for (int c = 0; c < 32; c++) {
            float qv[4];
#pragma unroll
            for (int i = 0; i < 4; i++) qv[i] = sQ[warp * 4 + i][c];
#pragma unroll
            for (int jj = 0; jj < 4; jj++) {
                float wv = sW[jj * 32 + lane][c];
#pragma unroll
                for (int i = 0; i < 4; i++) acc[i][jj] += wv * qv[i];
            }
        }
#pragma unroll
        for (int i = 0; i < 4; i++)
#pragma unroll
            for (int jj = 0; jj < 4; jj++)
                g_u[(size_t)(base + warp * 4 + i) * 512 + h * 128 + jj * 32 + lane]
                    = acc[i][jj] * scale;
        __syncthreads();
    }
}

// ---------------- attention v3: group-per-head, 3-shuffle reduction ----------------
// One warp per node. Lanes split into 4 groups of 8; group g owns head g.
// Each group reads the FULL 128-wide e_h row (16 ch/lane) so the e.u dot and the
// weighted e-accumulation stay entirely within the group.
__global__ void k_attn3(const float* __restrict__ q, const float* __restrict__ kk,
                        const float* __restrict__ vv, const float* __restrict__ sk)
{
    int wrp  = (blockIdx.x * blockDim.x + threadIdx.x) >> 5;
    int lane = threadIdx.x & 31;
    if (wrp >= NN) return;
    int g  = lane >> 3;     // head
    int l8 = lane & 7;      // lane within group
    const float scale = 0.17677669529663687f;

    // q chunk for own head (channels g*32 + l8*4 .. +3), pre-scaled
    float4 q4 = *(const float4*)(q + (size_t)wrp * 128 + g * 32 + l8 * 4);
    q4.x *= scale; q4.y *= scale; q4.z *= scale; q4.w *= scale;

    // u_g chunk: e_h-dims [l8*16 .. l8*16+15]
    float4 uR[4];
#pragma unroll
    for (int j = 0; j < 4; j++)
        uR[j] = *(const float4*)(g_u + (size_t)wrp * 512 + g * 128 + l8 * 16 + j * 4);

    float4 eacc[4];
#pragma unroll
    for (int j = 0; j < 4; j++) eacc[j] = make_float4(0.f, 0.f, 0.f, 0.f);
    float4 vacc = make_float4(0.f, 0.f, 0.f, 0.f);
    float ssum = 0.f;

    int beg = g_rowstart[wrp], end = g_rowstart[wrp + 1];
    int src = (beg < end) ? g_csrsrc[beg] : 0;

    for (int idx = beg; idx < end; ++idx) {
        int nsrc = (idx + 1 < end) ? g_csrsrc[idx + 1] : 0;

        // full e row per group: 4 x float4 (16 ch/lane)
        const float* erow = g_eh + (size_t)idx * 128 + l8 * 16;
        float4 e0 = *(const float4*)(erow + 0);
        float4 e1 = *(const float4*)(erow + 4);
        float4 e2 = *(const float4*)(erow + 8);
        float4 e3 = *(const float4*)(erow + 12);
        // k, v chunks for own head (coalesced across warp)
        float4 k4 = *(const float4*)(kk + (size_t)src * 128 + g * 32 + l8 * 4);
        float4 v4 = *(const float4*)(vv + (size_t)src * 128 + g * 32 + l8 * 4);

        float p = e0.x * uR[0].x + e0.y * uR[0].y + e0.z * uR[0].z + e0.w * uR[0].w
                + e1.x * uR[1].x + e1.y * uR[1].y + e1.z * uR[1].z + e1.w * uR[1].w
                + e2.x * uR[2].x + e2.y * uR[2].y + e2.z * uR[2].z + e2.w * uR[2].w
                + e3.x * uR[3].x + e3.y * uR[3].y + e3.z * uR[3].z + e3.w * uR[3].w
                + q4.x * k4.x + q4.y * k4.y + q4.z * k4.z + q4.w * k4.w;
        // intra-group (8-lane) reduction: full P for head g
        p += __shfl_xor_sync(0xffffffffu, p, 1);
        p += __shfl_xor_sync(0xffffffffu, p, 2);
        p += __shfl_xor_sync(0xffffffffu, p, 4);

        float w = __expf(p);
        ssum += w;
        vacc.x += w * v4.x; vacc.y += w * v4.y;
        vacc.z += w * v4.z; vacc.w += w * v4.w;
        eacc[0].x += w * e0.x; eacc[0].y += w * e0.y; eacc[0].z += w * e0.z; eacc[0].w += w * e0.w;
        eacc[1].x += w * e1.x; eacc[1].y += w * e1.y; eacc[1].z += w * e1.z; eacc[1].w += w * e1.w;
        eacc[2].x += w * e2.x; eacc[2].y += w * e2.y; eacc[2].z += w * e2.z; eacc[2].w += w * e2.w;
        eacc[3].x += w * e3.x; eacc[3].y += w * e3.y; eacc[3].z += w * e3.z; eacc[3].w += w * e3.w;

        src = nsrc;
    }

    float inv = 1.f / (ssum + 1e-16f);

    // tmpv: lane's v chunk channels g*32+l8*4 == 4*lane (same layout as before)
    float4 s4 = *(const float4*)(sk + (size_t)wrp * 128 + lane * 4);
    float4 t;
    t.x = vacc.x * inv + s4.x;
    t.y = vacc.y * inv + s4.y;
    t.z = vacc.z * inv + s4.z;
    t.w = vacc.w * inv + s4.w;
    *(float4*)(g_tmpv + (size_t)wrp * 128 + lane * 4) = t;

    float* aout = g_agg + (size_t)wrp * 512 + g * 128 + l8 * 16;
#pragma unroll
    for (int j = 0; j < 4; j++) {
        float4 a;
        a.x = eacc[j].x * inv; a.y = eacc[j].y * inv;
        a.z = eacc[j].z * inv; a.w = eacc[j].w * inv;
        *(float4*)(aout + j * 4) = a;
    }
}

// ---------------- post: out = tmpv + agg @ We, LN + ReLU ----------------
__global__ void k_post(const float* __restrict__ Wt,
                       const float* __restrict__ lng, const float* __restrict__ lnb,
                       float* __restrict__ hout)
{
    __shared__ float sagg[32][132];
    __shared__ float sW[32][132];
    int tid  = threadIdx.x;
    int warp = tid >> 5;
    int lane = tid & 31;
    int base = blockIdx.x * 32;

    float out[4][4];
#pragma unroll
    for (int i = 0; i < 4; i++)
#pragma unroll
        for (int h = 0; h < 4; h++)
            out[i][h] = g_tmpv[(size_t)(base + warp * 4 + i) * 128 + h * 32 + lane];

    for (int h = 0; h < 4; h++) {
        for (int idx = tid; idx < 1024; idx += 256) {
            int r = idx >> 5, c4 = idx & 31;
            *(float4*)&sW[r][c4 * 4]   = *(const float4*)&Wt[(size_t)(h * 32 + r) * 128 + c4 * 4];
            *(float4*)&sagg[r][c4 * 4] = *(const float4*)&g_agg[(size_t)(base + r) * 512 + h * 128 + c4 * 4];
        }
        __syncthreads();
#pragma unroll 4
        for (int j4 = 0; j4 < 32; j4++) {
            float4 w4 = *(float4*)&sW[lane][j4 * 4];
#pragma unroll
            for (int i = 0; i < 4; i++) {
                float4 a4 = *(float4*)&sagg[warp * 4 + i][j4 * 4];
                out[i][h] += w4.x * a4.x + w4.y * a4.y + w4.z * a4.z + w4.w * a4.w;
            }
        }
        __syncthreads();
    }

#pragma unroll
    for (int i = 0; i < 4; i++) {
        float s = out[i][0] + out[i][1] + out[i][2] + out[i][3];
#pragma unroll
        for (int off = 16; off; off >>= 1) s += __shfl_xor_sync(0xffffffffu, s, off);
        float mu = s * 0.0078125f;
        float d0 = out[i][0] - mu, d1 = out[i][1] - mu;
        float d2 = out[i][2] - mu, d3 = out[i][3] - mu;
        float sq = d0 * d0 + d1 * d1 + d2 * d2 + d3 * d3;
#pragma unroll
        for (int off = 16; off; off >>= 1) sq += __shfl_xor_sync(0xffffffffu, sq, off);
        float r = rsqrtf(sq * 0.0078125f + 1e-5f);
        size_t row = (size_t)(base + warp * 4 + i) * 128;
        float dd[4] = {d0, d1, d2, d3};
#pragma unroll
        for (int h = 0; h < 4; h++) {
            float gg = lng[h * 32 + lane], bb = lnb[h * 32 + lane];
            hout[row + h * 32 + lane] = fmaxf(0.f, dd[h] * r * gg + bb);
        }
    }
}

// ---------------- global mean pool + MLP heads ----------------
__global__ void k_pool(const float* __restrict__ h, const int* __restrict__ batch)
{
    int t = blockIdx.x * blockDim.x + threadIdx.x;
    if (t >= NN * HH) return;
    int n = t >> 7, c = t & 127;
    int b = batch[n];
    atomicAdd(&g_pool[b * HH + c], h[t]);
    if (c == 0) atomicAdd(&g_pcnt[b], 1.f);
}

__global__ void k_heads(const float* __restrict__ dw1, const float* __restrict__ db1,
                        const float* __restrict__ dw2, const float* __restrict__ db2,
                        const float* __restrict__ tw1, const float* __restrict__ tb1,
                        const float* __restrict__ tw2, const float* __restrict__ tb2,
                        float* __restrict__ out)
{
    const float* W1 = blockIdx.x ? tw1 : dw1;
    const float* B1 = blockIdx.x ? tb1 : db1;
    const float* W2 = blockIdx.x ? tw2 : dw2;
    const float* B2 = blockIdx.x ? tb2 : db2;

    __shared__ float hg[GG][HH];
    __shared__ float t1[GG][64];
    int t = threadIdx.x;

    for (int i = t; i < GG * HH; i += 256) {
        int g = i >> 7;
        hg[g][i & 127] = g_pool[i] / fmaxf(g_pcnt[g], 1.f);
    }
    __syncthreads();
    for (int i = t; i < GG * 64; i += 256) {
        int g = i >> 6, j = i & 63;
        float acc = B1[j];
        for (int c = 0; c < 128; c++) acc += hg[g][c] * W1[c * 64 + j];
        t1[g][j] = fmaxf(acc, 0.f);
    }
    __syncthreads();
    for (int i = t; i < GG * OO; i += 256) {
        int g = i / OO, o = i % OO;
        float acc = B2[o];
        for (int j = 0; j < 64; j++) acc += t1[g][j] * W2[j * OO + o];
        out[blockIdx.x * GG * OO + i] = acc;
    }
}

// ---------------- launch ----------------
extern "C" void kernel_launch(void* const* d_in, const int* in_sizes, int n_in,
                              void* d_out, int out_size)
{
    const float* x      = (const float*)d_in[0];
    const float* eattr  = (const float*)d_in[1];
    const float* node_w = (const float*)d_in[2];
    const float* node_b = (const float*)d_in[3];
    const float* edge_w = (const float*)d_in[4];
    const float* edge_b = (const float*)d_in[5];
    const float* Wq  = (const float*)d_in[6];
    const float* bq  = (const float*)d_in[7];
    const float* Wk  = (const float*)d_in[8];
    const float* bk  = (const float*)d_in[9];
    const float* Wv  = (const float*)d_in[10];
    const float* bv  = (const float*)d_in[11];
    const float* We  = (const float*)d_in[12];
    const float* Wsk = (const float*)d_in[13];
    const float* bsk = (const float*)d_in[14];
    const float* lng = (const float*)d_in[15];
    const float* lnb = (const float*)d_in[16];
    const float* dw1 = (const float*)d_in[17];
    const float* db1 = (const float*)d_in[18];
    const float* dw2 = (const float*)d_in[19];
    const float* db2 = (const float*)d_in[20];
    const float* tw1 = (const float*)d_in[21];
    const float* tb1 = (const float*)d_in[22];
    const float* tw2 = (const float*)d_in[23];
    const float* tb2 = (const float*)d_in[24];
    const int*   ei    = (const int*)d_in[25];
    const int*   batch = (const int*)d_in[26];
    float* out = (float*)d_out;

    float *hA, *hB, *qp, *kp, *vp, *sp, *wt;
    cudaGetSymbolAddress((void**)&hA, g_hA);
    cudaGetSymbolAddress((void**)&hB, g_hB);
    cudaGetSymbolAddress((void**)&qp, g_q);
    cudaGetSymbolAddress((void**)&kp, g_k);
    cudaGetSymbolAddress((void**)&vp, g_v);
    cudaGetSymbolAddress((void**)&sp, g_s);
    cudaGetSymbolAddress((void**)&wt, g_Wt);

    dim3 gg(NN / BM, 4);

    // gemm4 (layer 0) in the ncu-profiled slot (#4).
    k_zero<<<(NN + 255) / 256, 256>>>();
    k_hist<<<(EE + 255) / 256, 256>>>(ei);
    k_nodeproj<<<(NN * HH + 255) / 256, 256>>>(x, node_w, node_b);
    gemm4<<<gg, 128>>>(hA, Wq, Wk, Wv, Wsk, bq, bk, bv, bsk, qp, kp, vp, sp);
    k_scan<<<1, 1024>>>();
    k_scatter<<<(EE + 255) / 256, 256>>>(ei);
    k_edgeproj<<<(EE * HH + 255) / 256, 256>>>(eattr, edge_w, edge_b);
    k_trWe<<<(LL * HH * HH + 255) / 256, 256>>>(We);

    float* hcur = hA;
    float* hnxt = hB;
    for (int i = 0; i < LL; i++) {
        if (i > 0)
            gemm4<<<gg, 128>>>(hcur,
                               Wq + i * HH * HH, Wk + i * HH * HH,
                               Wv + i * HH * HH, Wsk + i * HH * HH,
                               bq + i * HH, bk + i * HH, bv + i * HH, bsk + i * HH,
                               qp, kp, vp, sp);
        k_uproj<<<NN / 32, 256>>>(qp, We + i * HH * HH);
        k_attn3<<<(NN * 32) / 256, 256>>>(qp, kp, vp, sp);
        k_post<<<NN / 32, 256>>>(wt + i * HH * HH, lng + i * HH, lnb + i * HH, hnxt);
        float* tmp = hcur; hcur = hnxt; hnxt = tmp;
    }

    k_pool<<<(NN * HH + 255) / 256, 256>>>(hcur, batch);
    k_heads<<<2, 256>>>(dw1, db1, dw2, db2, tw1, tb1, tw2, tb2, out);
}

// round 7
// speedup vs baseline: 1.1247x; 1.1247x over previous
#include <cuda_runtime.h>
#include <math.h>

#define NN 40000
#define EE 640000
#define GG 32
#define HH 128
#define LL 4
#define OO 100

// ---------------- device scratch ----------------
__device__ float g_hA[NN * HH];
__device__ float g_hB[NN * HH];
__device__ float g_eh[EE * HH];       // edge projection, CSR-permuted order
__device__ float g_q [NN * HH];
__device__ float g_k [NN * HH];
__device__ float g_v [NN * HH];
__device__ float g_s [NN * HH];
__device__ float g_u  [NN * 512];
__device__ float g_agg[NN * 512];
__device__ float g_tmpv[NN * HH];
__device__ float g_Wt[LL * HH * HH];
__device__ int   g_hist[NN];
__device__ int   g_rowstart[NN + 1];
__device__ int   g_cursor[NN];
__device__ int   g_edgepos[EE];
__device__ int   g_csrsrc[EE];
__device__ float g_pool[GG * HH];
__device__ float g_pcnt[GG];

// ---------------- CSR construction ----------------
__global__ void k_zero()
{
    int i = blockIdx.x * blockDim.x + threadIdx.x;
    if (i < NN) g_hist[i] = 0;
    if (i < GG * HH) g_pool[i] = 0.f;
    if (i < GG) g_pcnt[i] = 0.f;
}

__global__ void k_hist(const int* __restrict__ ei)
{
    int e = blockIdx.x * blockDim.x + threadIdx.x;
    if (e < EE) atomicAdd(&g_hist[ei[EE + e]], 1);
}

__global__ void k_scan()
{
    const int T = 1024, CH = 40;
    __shared__ int sh[T];
    int t = threadIdx.x;
    int base = t * CH;
    int loc[CH];
    int run = 0;
#pragma unroll
    for (int i = 0; i < CH; i++) {
        int idx = base + i;
        int vv = (idx < NN) ? g_hist[idx] : 0;
        loc[i] = run;
        run += vv;
    }
    sh[t] = run;
    __syncthreads();
    for (int off = 1; off < T; off <<= 1) {
        int vv = (t >= off) ? sh[t - off] : 0;
        __syncthreads();
        sh[t] += vv;
        __syncthreads();
    }
    int offset = (t > 0) ? sh[t - 1] : 0;
#pragma unroll
    for (int i = 0; i < CH; i++) {
        int idx = base + i;
        if (idx < NN) {
            int p = offset + loc[i];
            g_rowstart[idx] = p;
            g_cursor[idx]   = p;
        }
    }
    if (t == T - 1) g_rowstart[NN] = sh[T - 1];
}

__global__ void k_scatter(const int* __restrict__ ei)
{
    int e = blockIdx.x * blockDim.x + threadIdx.x;
    if (e < EE) {
        int dst = ei[EE + e];
        int pos = atomicAdd(&g_cursor[dst], 1);
        g_edgepos[e] = pos;
        g_csrsrc[pos] = ei[e];
    }
}

// ---------------- input projections ----------------
__global__ void k_nodeproj(const float* __restrict__ x,
                           const float* __restrict__ w,
                           const float* __restrict__ b)
{
    int t = blockIdx.x * blockDim.x + threadIdx.x;
    if (t >= NN * HH) return;
    int n = t >> 7, c = t & 127;
    const float* xr = x + n * 4;
    float acc = b[c];
    acc += xr[0] * w[c] + xr[1] * w[128 + c] + xr[2] * w[256 + c] + xr[3] * w[384 + c];
    g_hA[t] = acc;
}

__global__ void k_edgeproj(const float* __restrict__ ea,
                           const float* __restrict__ w,
                           const float* __restrict__ b)
{
    int t = blockIdx.x * blockDim.x + threadIdx.x;
    if (t >= EE * HH) return;
    int e = t >> 7, c = t & 127;
    const float* ar = ea + e * 5;
    float acc = b[c];
#pragma unroll
    for (int j = 0; j < 5; j++) acc += ar[j] * w[j * 128 + c];
    int pos = g_edgepos[e];
    g_eh[pos * HH + c] = acc;
}

__global__ void k_trWe(const float* __restrict__ We)
{
    int t = blockIdx.x * blockDim.x + threadIdx.x;
    if (t >= LL * HH * HH) return;
    int l = t >> 14;
    int rem = t & 16383;
    int c = rem >> 7, j = rem & 127;
    g_Wt[t] = We[l * HH * HH + j * HH + c];
}

// ---------------- fused 4-matrix GEMM ----------------
#define BM 64
#define BK 16

__global__ void gemm4(const float* __restrict__ A,
                      const float* __restrict__ B0, const float* __restrict__ B1,
                      const float* __restrict__ B2, const float* __restrict__ B3,
                      const float* __restrict__ c0, const float* __restrict__ c1,
                      const float* __restrict__ c2, const float* __restrict__ c3,
                      float* __restrict__ C0, float* __restrict__ C1,
                      float* __restrict__ C2, float* __restrict__ C3)
{
    const float* B    = (blockIdx.y == 0) ? B0 : (blockIdx.y == 1) ? B1 : (blockIdx.y == 2) ? B2 : B3;
    const float* bias = (blockIdx.y == 0) ? c0 : (blockIdx.y == 1) ? c1 : (blockIdx.y == 2) ? c2 : c3;
    float* C          = (blockIdx.y == 0) ? C0 : (blockIdx.y == 1) ? C1 : (blockIdx.y == 2) ? C2 : C3;

    __shared__ float As[BK][BM + 4];
    __shared__ float Bs[BK][128];
    int tid  = threadIdx.x;
    int tcol = tid & 15;
    int trow = tid >> 4;
    int block_m = blockIdx.x * BM;

    float acc[8][8];
#pragma unroll
    for (int i = 0; i < 8; i++)
#pragma unroll
        for (int j = 0; j < 8; j++) acc[i][j] = 0.f;

    for (int k0 = 0; k0 < 128; k0 += BK) {
#pragma unroll
        for (int it = 0; it < 2; it++) {
            int f = tid + it * 128;
            int row = f >> 2;
            int kq  = f & 3;
            float4 a = *(const float4*)&A[(size_t)(block_m + row) * 128 + k0 + kq * 4];
            As[kq * 4 + 0][row] = a.x;
            As[kq * 4 + 1][row] = a.y;
            As[kq * 4 + 2][row] = a.z;
            As[kq * 4 + 3][row] = a.w;
        }
#pragma unroll
        for (int it = 0; it < 4; it++) {
            int f = tid + it * 128;
            int krow = f >> 5;
            int nq   = f & 31;
            *(float4*)&Bs[krow][nq * 4] = *(const float4*)&B[(k0 + krow) * 128 + nq * 4];
        }
        __syncthreads();
#pragma unroll
        for (int k = 0; k < BK; k++) {
            float a[8], b[8];
            *(float4*)&a[0] = *(float4*)&As[k][trow * 4];
            *(float4*)&a[4] = *(float4*)&As[k][32 + trow * 4];
            *(float4*)&b[0] = *(float4*)&Bs[k][tcol * 4];
            *(float4*)&b[4] = *(float4*)&Bs[k][64 + tcol * 4];
#pragma unroll
            for (int i = 0; i < 8; i++)
#pragma unroll
                for (int j = 0; j < 8; j++)
                    acc[i][j] += a[i] * b[j];
        }
        __syncthreads();
    }

    float4 bLo = *(const float4*)&bias[tcol * 4];
    float4 bHi = *(const float4*)&bias[64 + tcol * 4];
#pragma unroll
    for (int i = 0; i < 8; i++) {
        int row = block_m + ((i < 4) ? (trow * 4 + i) : (32 + trow * 4 + i - 4));
        float4 lo, hi;
        lo.x = acc[i][0] + bLo.x; lo.y = acc[i][1] + bLo.y;
        lo.z = acc[i][2] + bLo.z; lo.w = acc[i][3] + bLo.w;
        hi.x = acc[i][4] + bHi.x; hi.y = acc[i][5] + bHi.y;
        hi.z = acc[i][6] + bHi.z; hi.w = acc[i][7] + bHi.w;
        *(float4*)&C[(size_t)row * 128 + tcol * 4]      = lo;
        *(float4*)&C[(size_t)row * 128 + 64 + tcol * 4] = hi;
    }
}

// ---------------- u kernel ----------------
__global__ void k_uproj(const float* __restrict__ q, const float* __restrict__ We)
{
    __shared__ float sW[128][33];
    __shared__ float sQ[32][32];
    const float scale = 0.17677669529663687f;
    int tid  = threadIdx.x;
    int warp = tid >> 5;
    int lane = tid & 31;
    int base = blockIdx.x * 32;

    for (int h = 0; h < 4; h++) {
        for (int idx = tid; idx < 128 * 8; idx += 256) {
            int j = idx >> 3, c4 = idx & 7;
            float4 w4 = *(const float4*)&We[j * 128 + h * 32 + c4 * 4];
            sW[j][c4 * 4 + 0] = w4.x;
            sW[j][c4 * 4 + 1] = w4.y;
            sW[j][c4 * 4 + 2] = w4.z;
            sW[j][c4 * 4 + 3] = w4.w;
        }
        for (int idx = tid; idx < 32 * 8; idx += 256) {
            int n = idx >> 3, c4 = idx & 7;
            float4 q4 = *(const float4*)&q[(size_t)(base + n) * 128 + h * 32 + c4 * 4];
            sQ[n][c4 * 4 + 0] = q4.x;
            sQ[n][c4 * 4 + 1] = q4.y;
            sQ[n][c4 * 4 + 2] = q4.z;
            sQ[n][c4 * 4 + 3] = q4.w;
        }
        __syncthreads();

        float acc[4][4];
#pragma unroll
        for (int i = 0; i < 4; i++)
#pragma unroll
            for (int jj = 0; jj < 4; jj++) acc[i][jj] = 0.f;

        for (int c = 0; c < 32; c++) {
            float qv[4];
#pragma unroll
            for (int i = 0; i < 4; i++) qv[i] = sQ[warp * 4 + i][c];
#pragma unroll
            for (int jj = 0; jj < 4; jj++) {
                float wv = sW[jj * 32 + lane][c];
#pragma unroll
                for (int i = 0; i < 4; i++) acc[i][jj] += wv * qv[i];
            }
        }
#pragma unroll
        for (int i = 0; i < 4; i++)
#pragma unroll
            for (int jj = 0; jj < 4; jj++)
                g_u[(size_t)(base + warp * 4 + i) * 512 + h * 128 + jj * 32 + lane]
                    = acc[i][jj] * scale;
        __syncthreads();
    }
}

// ---------------- attention v4: attn2 layout, cheap reduction, 2-edge unroll -------------
// Reduction: jointly reduce 4 per-head partials across groups (xor16, xor8),
// then each 8-lane group finishes ONLY its own head (xor1,2,4), computes one exp,
// and the other heads' weights are recovered via xor8/xor16 exchanges + selects.
__global__ void k_attn2(const float* __restrict__ q, const float* __restrict__ kk,
                        const float* __restrict__ vv, const float* __restrict__ sk)
{
    int wrp  = (blockIdx.x * blockDim.x + threadIdx.x) >> 5;
    int lane = threadIdx.x & 31;
    if (wrp >= NN) return;
    int g = lane >> 3;
    const float scale = 0.17677669529663687f;
    const unsigned FULL = 0xffffffffu;

    float4 q4 = *(const float4*)(q + (size_t)wrp * 128 + lane * 4);
    q4.x *= scale; q4.y *= scale; q4.z *= scale; q4.w *= scale;
    float4 u0 = *(const float4*)(g_u + (size_t)wrp * 512 +   0 + lane * 4);
    float4 u1 = *(const float4*)(g_u + (size_t)wrp * 512 + 128 + lane * 4);
    float4 u2 = *(const float4*)(g_u + (size_t)wrp * 512 + 256 + lane * 4);
    float4 u3 = *(const float4*)(g_u + (size_t)wrp * 512 + 384 + lane * 4);

    float s0 = 0.f, s1 = 0.f, s2 = 0.f, s3 = 0.f;
    float4 e0 = make_float4(0.f, 0.f, 0.f, 0.f), e1 = e0, e2 = e0, e3 = e0;
    float4 vacc = e0;

    int beg = g_rowstart[wrp], end = g_rowstart[wrp + 1];
    int idx = beg;

    for (; idx + 1 < end; idx += 2) {
        int sA = g_csrsrc[idx];
        int sB = g_csrsrc[idx + 1];
        float4 eA = *(const float4*)(g_eh + (size_t)idx * 128 + lane * 4);
        float4 eB = *(const float4*)(g_eh + (size_t)(idx + 1) * 128 + lane * 4);
        float4 kA = *(const float4*)(kk + (size_t)sA * 128 + lane * 4);
        float4 kB = *(const float4*)(kk + (size_t)sB * 128 + lane * 4);
        float4 vA = *(const float4*)(vv + (size_t)sA * 128 + lane * 4);
        float4 vB = *(const float4*)(vv + (size_t)sB * 128 + lane * 4);

        float A0 = eA.x * u0.x + eA.y * u0.y + eA.z * u0.z + eA.w * u0.w;
        float A1 = eA.x * u1.x + eA.y * u1.y + eA.z * u1.z + eA.w * u1.w;
        float A2 = eA.x * u2.x + eA.y * u2.y + eA.z * u2.z + eA.w * u2.w;
        float A3 = eA.x * u3.x + eA.y * u3.y + eA.z * u3.z + eA.w * u3.w;
        float B0 = eB.x * u0.x + eB.y * u0.y + eB.z * u0.z + eB.w * u0.w;
        float B1 = eB.x * u1.x + eB.y * u1.y + eB.z * u1.z + eB.w * u1.w;
        float B2 = eB.x * u2.x + eB.y * u2.y + eB.z * u2.z + eB.w * u2.w;
        float B3 = eB.x * u3.x + eB.y * u3.y + eB.z * u3.z + eB.w * u3.w;
        float pA = q4.x * kA.x + q4.y * kA.y + q4.z * kA.z + q4.w * kA.w;
        float pB = q4.x * kB.x + q4.y * kB.y + q4.z * kB.z + q4.w * kB.w;
        A0 += (g == 0) ? pA : 0.f;  B0 += (g == 0) ? pB : 0.f;
        A1 += (g == 1) ? pA : 0.f;  B1 += (g == 1) ? pB : 0.f;
        A2 += (g == 2) ? pA : 0.f;  B2 += (g == 2) ? pB : 0.f;
        A3 += (g == 3) ? pA : 0.f;  B3 += (g == 3) ? pB : 0.f;

        // joint cross-group reduction (per l8-slot partials)
        A0 += __shfl_xor_sync(FULL, A0, 16); B0 += __shfl_xor_sync(FULL, B0, 16);
        A1 += __shfl_xor_sync(FULL, A1, 16); B1 += __shfl_xor_sync(FULL, B1, 16);
        A2 += __shfl_xor_sync(FULL, A2, 16); B2 += __shfl_xor_sync(FULL, B2, 16);
        A3 += __shfl_xor_sync(FULL, A3, 16); B3 += __shfl_xor_sync(FULL, B3, 16);
        A0 += __shfl_xor_sync(FULL, A0, 8);  B0 += __shfl_xor_sync(FULL, B0, 8);
        A1 += __shfl_xor_sync(FULL, A1, 8);  B1 += __shfl_xor_sync(FULL, B1, 8);
        A2 += __shfl_xor_sync(FULL, A2, 8);  B2 += __shfl_xor_sync(FULL, B2, 8);
        A3 += __shfl_xor_sync(FULL, A3, 8);  B3 += __shfl_xor_sync(FULL, B3, 8);

        // own-head finish within group
        float PA = (g == 0) ? A0 : (g == 1) ? A1 : (g == 2) ? A2 : A3;
        float PB = (g == 0) ? B0 : (g == 1) ? B1 : (g == 2) ? B2 : B3;
        PA += __shfl_xor_sync(FULL, PA, 1);  PB += __shfl_xor_sync(FULL, PB, 1);
        PA += __shfl_xor_sync(FULL, PA, 2);  PB += __shfl_xor_sync(FULL, PB, 2);
        PA += __shfl_xor_sync(FULL, PA, 4);  PB += __shfl_xor_sync(FULL, PB, 4);

        float wA = __expf(PA);
        float wB = __expf(PB);

        // gather other heads' weights
        float waA = __shfl_xor_sync(FULL, wA, 8);   // head g^1
        float waB = __shfl_xor_sync(FULL, wB, 8);
        float wbA = __shfl_xor_sync(FULL, wA, 16);  // head g^2
        float wbB = __shfl_xor_sync(FULL, wB, 16);
        float wcA = __shfl_xor_sync(FULL, waA, 16); // head g^3
        float wcB = __shfl_xor_sync(FULL, waB, 16);

        float w0A = (g == 0) ? wA : (g == 1) ? waA : (g == 2) ? wbA : wcA;
        float w1A = (g == 1) ? wA : (g == 0) ? waA : (g == 3) ? wbA : wcA;
        float w2A = (g == 2) ? wA : (g == 3) ? waA : (g == 0) ? wbA : wcA;
        float w3A = (g == 3) ? wA : (g == 2) ? waA : (g == 1) ? wbA : wcA;
        float w0B = (g == 0) ? wB : (g == 1) ? waB : (g == 2) ? wbB : wcB;
        float w1B = (g == 1) ? wB : (g == 0) ? waB : (g == 3) ? wbB : wcB;
        float w2B = (g == 2) ? wB : (g == 3) ? waB : (g == 0) ? wbB : wcB;
        float w3B = (g == 3) ? wB : (g == 2) ? waB : (g == 1) ? wbB : wcB;

        s0 += w0A + w0B; s1 += w1A + w1B; s2 += w2A + w2B; s3 += w3A + w3B;

        e0.x += w0A * eA.x + w0B * eB.x; e0.y += w0A * eA.y + w0B * eB.y;
        e0.z += w0A * eA.z + w0B * eB.z; e0.w += w0A * eA.w + w0B * eB.w;
        e1.x += w1A * eA.x + w1B * eB.x; e1.y += w1A * eA.y + w1B * eB.y;
        e1.z += w1A * eA.z + w1B * eB.z; e1.w += w1A * eA.w + w1B * eB.w;
        e2.x += w2A * eA.x + w2B * eB.x; e2.y += w2A * eA.y + w2B * eB.y;
        e2.z += w2A * eA.z + w2B * eB.z; e2.w += w2A * eA.w + w2B * eB.w;
        e3.x += w3A * eA.x + w3B * eB.x; e3.y += w3A * eA.y + w3B * eB.y;
        e3.z += w3A * eA.z + w3B * eB.z; e3.w += w3A * eA.w + w3B * eB.w;

        float wgA = wA, wgB = wB;   // own head's weight
        vacc.x += wgA * vA.x + wgB * vB.x;
        vacc.y += wgA * vA.y + wgB * vB.y;
        vacc.z += wgA * vA.z + wgB * vB.z;
        vacc.w += wgA * vA.w + wgB * vB.w;
    }

    if (idx < end) {
        int sA = g_csrsrc[idx];
        float4 eA = *(const float4*)(g_eh + (size_t)idx * 128 + lane * 4);
        float4 kA = *(const float4*)(kk + (size_t)sA * 128 + lane * 4);
        float4 vA = *(const float4*)(vv + (size_t)sA * 128 + lane * 4);

        float A0 = eA.x * u0.x + eA.y * u0.y + eA.z * u0.z + eA.w * u0.w;
        float A1 = eA.x * u1.x + eA.y * u1.y + eA.z * u1.z + eA.w * u1.w;
        float A2 = eA.x * u2.x + eA.y * u2.y + eA.z * u2.z + eA.w * u2.w;
        float A3 = eA.x * u3.x + eA.y * u3.y + eA.z * u3.z + eA.w * u3.w;
        float pA = q4.x * kA.x + q4.y * kA.y + q4.z * kA.z + q4.w * kA.w;
        A0 += (g == 0) ? pA : 0.f;
        A1 += (g == 1) ? pA : 0.f;
        A2 += (g == 2) ? pA : 0.f;
        A3 += (g == 3) ? pA : 0.f;

        A0 += __shfl_xor_sync(FULL, A0, 16);
        A1 += __shfl_xor_sync(FULL, A1, 16);
        A2 += __shfl_xor_sync(FULL, A2, 16);
        A3 += __shfl_xor_sync(FULL, A3, 16);
        A0 += __shfl_xor_sync(FULL, A0, 8);
        A1 += __shfl_xor_sync(FULL, A1, 8);
        A2 += __shfl_xor_sync(FULL, A2, 8);
        A3 += __shfl_xor_sync(FULL, A3, 8);

        float PA = (g == 0) ? A0 : (g == 1) ? A1 : (g == 2) ? A2 : A3;
        PA += __shfl_xor_sync(FULL, PA, 1);
        PA += __shfl_xor_sync(FULL, PA, 2);
        PA += __shfl_xor_sync(FULL, PA, 4);

        float wA = __expf(PA);
        float waA = __shfl_xor_sync(FULL, wA, 8);
        float wbA = __shfl_xor_sync(FULL, wA, 16);
        float wcA = __shfl_xor_sync(FULL, waA, 16);

        float w0A = (g == 0) ? wA : (g == 1) ? waA : (g == 2) ? wbA : wcA;
        float w1A = (g == 1) ? wA : (g == 0) ? waA : (g == 3) ? wbA : wcA;
        float w2A = (g == 2) ? wA : (g == 3) ? waA : (g == 0) ? wbA : wcA;
        float w3A = (g == 3) ? wA : (g == 2) ? waA : (g == 1) ? wbA : wcA;

        s0 += w0A; s1 += w1A; s2 += w2A; s3 += w3A;
        e0.x += w0A * eA.x; e0.y += w0A * eA.y; e0.z += w0A * eA.z; e0.w += w0A * eA.w;
        e1.x += w1A * eA.x; e1.y += w1A * eA.y; e1.z += w1A * eA.z; e1.w += w1A * eA.w;
        e2.x += w2A * eA.x; e2.y += w2A * eA.y; e2.z += w2A * eA.z; e2.w += w2A * eA.w;
        e3.x += w3A * eA.x; e3.y += w3A * eA.y; e3.z += w3A * eA.z; e3.w += w3A * eA.w;
        vacc.x += wA * vA.x; vacc.y += wA * vA.y;
        vacc.z += wA * vA.z; vacc.w += wA * vA.w;
    }

    float sg  = (g == 0) ? s0 : (g == 1) ? s1 : (g == 2) ? s2 : s3;
    float ivg = 1.f / (sg + 1e-16f);
    float4 s4 = *(const float4*)(sk + (size_t)wrp * 128 + lane * 4);
    float4 t;
    t.x = vacc.x * ivg + s4.x;
    t.y = vacc.y * ivg + s4.y;
    t.z = vacc.z * ivg + s4.z;
    t.w = vacc.w * ivg + s4.w;
    *(float4*)(g_tmpv + (size_t)wrp * 128 + lane * 4) = t;

    float i0 = 1.f / (s0 + 1e-16f), i1 = 1.f / (s1 + 1e-16f);
    float i2 = 1.f / (s2 + 1e-16f), i3 = 1.f / (s3 + 1e-16f);
    float4 a;
    a.x = e0.x * i0; a.y = e0.y * i0; a.z = e0.z * i0; a.w = e0.w * i0;
    *(float4*)(g_agg + (size_t)wrp * 512 +   0 + lane * 4) = a;
    a.x = e1.x * i1; a.y = e1.y * i1; a.z = e1.z * i1; a.w = e1.w * i1;
    *(float4*)(g_agg + (size_t)wrp * 512 + 128 + lane * 4) = a;
    a.x = e2.x * i2; a.y = e2.y * i2; a.z = e2.z * i2; a.w = e2.w * i2;
    *(float4*)(g_agg + (size_t)wrp * 512 + 256 + lane * 4) = a;
    a.x = e3.x * i3; a.y = e3.y * i3; a.z = e3.z * i3; a.w = e3.w * i3;
    *(float4*)(g_agg + (size_t)wrp * 512 + 384 + lane * 4) = a;
}

// ---------------- post: out = tmpv + agg @ We, LN + ReLU ----------------
__global__ void k_post(const float* __restrict__ Wt,
                       const float* __restrict__ lng, const float* __restrict__ lnb,
                       float* __restrict__ hout)
{
    __shared__ float sagg[32][132];
    __shared__ float sW[32][132];
    int tid  = threadIdx.x;
    int warp = tid >> 5;
    int lane = tid & 31;
    int base = blockIdx.x * 32;

    float out[4][4];
#pragma unroll
    for (int i = 0; i < 4; i++)
#pragma unroll
        for (int h = 0; h < 4; h++)
            out[i][h] = g_tmpv[(size_t)(base + warp * 4 + i) * 128 + h * 32 + lane];

    for (int h = 0; h < 4; h++) {
        for (int idx = tid; idx < 1024; idx += 256) {
            int r = idx >> 5, c4 = idx & 31;
            *(float4*)&sW[r][c4 * 4]   = *(const float4*)&Wt[(size_t)(h * 32 + r) * 128 + c4 * 4];
            *(float4*)&sagg[r][c4 * 4] = *(const float4*)&g_agg[(size_t)(base + r) * 512 + h * 128 + c4 * 4];
        }
        __syncthreads();
#pragma unroll 4
        for (int j4 = 0; j4 < 32; j4++) {
            float4 w4 = *(float4*)&sW[lane][j4 * 4];
#pragma unroll
            for (int i = 0; i < 4; i++) {
                float4 a4 = *(float4*)&sagg[warp * 4 + i][j4 * 4];
                out[i][h] += w4.x * a4.x + w4.y * a4.y + w4.z * a4.z + w4.w * a4.w;
            }
        }
        __syncthreads();
    }

#pragma unroll
    for (int i = 0; i < 4; i++) {
        float s = out[i][0] + out[i][1] + out[i][2] + out[i][3];
#pragma unroll
        for (int off = 16; off; off >>= 1) s += __shfl_xor_sync(0xffffffffu, s, off);
        float mu = s * 0.0078125f;
        float d0 = out[i][0] - mu, d1 = out[i][1] - mu;
        float d2 = out[i][2] - mu, d3 = out[i][3] - mu;
        float sq = d0 * d0 + d1 * d1 + d2 * d2 + d3 * d3;
#pragma unroll
        for (int off = 16; off; off >>= 1) sq += __shfl_xor_sync(0xffffffffu, sq, off);
        float r = rsqrtf(sq * 0.0078125f + 1e-5f);
        size_t row = (size_t)(base + warp * 4 + i) * 128;
        float dd[4] = {d0, d1, d2, d3};
#pragma unroll
        for (int h = 0; h < 4; h++) {
            float gg = lng[h * 32 + lane], bb = lnb[h * 32 + lane];
            hout[row + h * 32 + lane] = fmaxf(0.f, dd[h] * r * gg + bb);
        }
    }
}

// ---------------- global mean pool + MLP heads ----------------
__global__ void k_pool(const float* __restrict__ h, const int* __restrict__ batch)
{
    int t = blockIdx.x * blockDim.x + threadIdx.x;
    if (t >= NN * HH) return;
    int n = t >> 7, c = t & 127;
    int b = batch[n];
    atomicAdd(&g_pool[b * HH + c], h[t]);
    if (c == 0) atomicAdd(&g_pcnt[b], 1.f);
}

__global__ void k_heads(const float* __restrict__ dw1, const float* __restrict__ db1,
                        const float* __restrict__ dw2, const float* __restrict__ db2,
                        const float* __restrict__ tw1, const float* __restrict__ tb1,
                        const float* __restrict__ tw2, const float* __restrict__ tb2,
                        float* __restrict__ out)
{
    const float* W1 = blockIdx.x ? tw1 : dw1;
    const float* B1 = blockIdx.x ? tb1 : db1;
    const float* W2 = blockIdx.x ? tw2 : dw2;
    const float* B2 = blockIdx.x ? tb2 : db2;

    __shared__ float hg[GG][HH];
    __shared__ float t1[GG][64];
    int t = threadIdx.x;

    for (int i = t; i < GG * HH; i += 256) {
        int g = i >> 7;
        hg[g][i & 127] = g_pool[i] / fmaxf(g_pcnt[g], 1.f);
    }
    __syncthreads();
    for (int i = t; i < GG * 64; i += 256) {
        int g = i >> 6, j = i & 63;
        float acc = B1[j];
        for (int c = 0; c < 128; c++) acc += hg[g][c] * W1[c * 64 + j];
        t1[g][j] = fmaxf(acc, 0.f);
    }
    __syncthreads();
    for (int i = t; i < GG * OO; i += 256) {
        int g = i / OO, o = i % OO;
        float acc = B2[o];
        for (int j = 0; j < 64; j++) acc += t1[g][j] * W2[j * OO + o];
        out[blockIdx.x * GG * OO + i] = acc;
    }
}

// ---------------- launch ----------------
extern "C" void kernel_launch(void* const* d_in, const int* in_sizes, int n_in,
                              void* d_out, int out_size)
{
    const float* x      = (const float*)d_in[0];
    const float* eattr  = (const float*)d_in[1];
    const float* node_w = (const float*)d_in[2];
    const float* node_b = (const float*)d_in[3];
    const float* edge_w = (const float*)d_in[4];
    const float* edge_b = (const float*)d_in[5];
    const float* Wq  = (const float*)d_in[6];
    const float* bq  = (const float*)d_in[7];
    const float* Wk  = (const float*)d_in[8];
    const float* bk  = (const float*)d_in[9];
    const float* Wv  = (const float*)d_in[10];
    const float* bv  = (const float*)d_in[11];
    const float* We  = (const float*)d_in[12];
    const float* Wsk = (const float*)d_in[13];
    const float* bsk = (const float*)d_in[14];
    const float* lng = (const float*)d_in[15];
    const float* lnb = (const float*)d_in[16];
    const float* dw1 = (const float*)d_in[17];
    const float* db1 = (const float*)d_in[18];
    const float* dw2 = (const float*)d_in[19];
    const float* db2 = (const float*)d_in[20];
    const float* tw1 = (const float*)d_in[21];
    const float* tb1 = (const float*)d_in[22];
    const float* tw2 = (const float*)d_in[23];
    const float* tb2 = (const float*)d_in[24];
    const int*   ei    = (const int*)d_in[25];
    const int*   batch = (const int*)d_in[26];
    float* out = (float*)d_out;

    float *hA, *hB, *qp, *kp, *vp, *sp, *wt;
    cudaGetSymbolAddress((void**)&hA, g_hA);
    cudaGetSymbolAddress((void**)&hB, g_hB);
    cudaGetSymbolAddress((void**)&qp, g_q);
    cudaGetSymbolAddress((void**)&kp, g_k);
    cudaGetSymbolAddress((void**)&vp, g_v);
    cudaGetSymbolAddress((void**)&sp, g_s);
    cudaGetSymbolAddress((void**)&wt, g_Wt);

    dim3 gg(NN / BM, 4);

    k_zero<<<(NN + 255) / 256, 256>>>();
    k_hist<<<(EE + 255) / 256, 256>>>(ei);
    k_nodeproj<<<(NN * HH + 255) / 256, 256>>>(x, node_w, node_b);
    gemm4<<<gg, 128>>>(hA, Wq, Wk, Wv, Wsk, bq, bk, bv, bsk, qp, kp, vp, sp);
    k_scan<<<1, 1024>>>();
    k_scatter<<<(EE + 255) / 256, 256>>>(ei);
    k_edgeproj<<<(EE * HH + 255) / 256, 256>>>(eattr, edge_w, edge_b);
    k_trWe<<<(LL * HH * HH + 255) / 256, 256>>>(We);

    float* hcur = hA;
    float* hnxt = hB;
    for (int i = 0; i < LL; i++) {
        if (i > 0)
            gemm4<<<gg, 128>>>(hcur,
                               Wq + i * HH * HH, Wk + i * HH * HH,
                               Wv + i * HH * HH, Wsk + i * HH * HH,
                               bq + i * HH, bk + i * HH, bv + i * HH, bsk + i * HH,
                               qp, kp, vp, sp);
        k_uproj<<<NN / 32, 256>>>(qp, We + i * HH * HH);
        k_attn2<<<(NN * 32) / 256, 256>>>(qp, kp, vp, sp);
        k_post<<<NN / 32, 256>>>(wt + i * HH * HH, lng + i * HH, lnb + i * HH, hnxt);
        float* tmp = hcur; hcur = hnxt; hnxt = tmp;
    }

    k_pool<<<(NN * HH + 255) / 256, 256>>>(hcur, batch);
    k_heads<<<2, 256>>>(dw1, db1, dw2, db2, tw1, tb1, tw2, tb2, out);
}

// round 9
// speedup vs baseline: 1.2113x; 1.0770x over previous
#include <cuda_runtime.h>
#include <math.h>

#define NN 40000
#define EE 640000
#define GG 32
#define HH 128
#define LL 4
#define OO 100

// ---------------- device scratch ----------------
__device__ float g_hA[NN * HH];
__device__ float g_hB[NN * HH];
__device__ float g_eh[EE * HH];       // edge projection, CSR-permuted order
__device__ float g_q [NN * HH];
__device__ float g_k [NN * HH];
__device__ float g_v [NN * HH];
__device__ float g_s [NN * HH];
__device__ float g_u  [NN * 512];
__device__ float g_agg[NN * 512];
__device__ float g_tmpv[NN * HH];
__device__ float g_og [NN * HH];          // agg @ We (post-GEMM result)
__device__ float g_Wtu[LL * 4 * 32 * HH]; // Wtu[l,h,c,j] = scale * We[l][j][h*32+c]
__device__ int   g_hist[NN];
__device__ int   g_rowstart[NN + 1];
__device__ int   g_cursor[NN];
__device__ int   g_edgepos[EE];
__device__ int   g_csrsrc[EE];
__device__ float g_pool[GG * HH];
__device__ float g_pcnt[GG];

// ---------------- CSR construction ----------------
__global__ void k_zero()
{
    int i = blockIdx.x * blockDim.x + threadIdx.x;
    if (i < NN) g_hist[i] = 0;
    if (i < GG * HH) g_pool[i] = 0.f;
    if (i < GG) g_pcnt[i] = 0.f;
}

__global__ void k_hist(const int* __restrict__ ei)
{
    int e = blockIdx.x * blockDim.x + threadIdx.x;
    if (e < EE) atomicAdd(&g_hist[ei[EE + e]], 1);
}

__global__ void k_scan()
{
    const int T = 1024, CH = 40;
    __shared__ int sh[T];
    int t = threadIdx.x;
    int base = t * CH;
    int loc[CH];
    int run = 0;
#pragma unroll
    for (int i = 0; i < CH; i++) {
        int idx = base + i;
        int vv = (idx < NN) ? g_hist[idx] : 0;
        loc[i] = run;
        run += vv;
    }
    sh[t] = run;
    __syncthreads();
    for (int off = 1; off < T; off <<= 1) {
        int vv = (t >= off) ? sh[t - off] : 0;
        __syncthreads();
        sh[t] += vv;
        __syncthreads();
    }
    int offset = (t > 0) ? sh[t - 1] : 0;
#pragma unroll
    for (int i = 0; i < CH; i++) {
        int idx = base + i;
        if (idx < NN) {
            int p = offset + loc[i];
            g_rowstart[idx] = p;
            g_cursor[idx]   = p;
        }
    }
    if (t == T - 1) g_rowstart[NN] = sh[T - 1];
}

__global__ void k_scatter(const int* __restrict__ ei)
{
    int e = blockIdx.x * blockDim.x + threadIdx.x;
    if (e < EE) {
        int dst = ei[EE + e];
        int pos = atomicAdd(&g_cursor[dst], 1);
        g_edgepos[e] = pos;
        g_csrsrc[pos] = ei[e];
    }
}

// ---------------- input projections / weight prep ----------------
__global__ void k_nodeproj(const float* __restrict__ x,
                           const float* __restrict__ w,
                           const float* __restrict__ b)
{
    int t = blockIdx.x * blockDim.x + threadIdx.x;
    if (t >= NN * HH) return;
    int n = t >> 7, c = t & 127;
    const float* xr = x + n * 4;
    float acc = b[c];
    acc += xr[0] * w[c] + xr[1] * w[128 + c] + xr[2] * w[256 + c] + xr[3] * w[384 + c];
    g_hA[t] = acc;
}

__global__ void k_edgeproj(const float* __restrict__ ea,
                           const float* __restrict__ w,
                           const float* __restrict__ b)
{
    int t = blockIdx.x * blockDim.x + threadIdx.x;
    if (t >= EE * HH) return;
    int e = t >> 7, c = t & 127;
    const float* ar = ea + e * 5;
    float acc = b[c];
#pragma unroll
    for (int j = 0; j < 5; j++) acc += ar[j] * w[j * 128 + c];
    int pos = g_edgepos[e];
    g_eh[pos * HH + c] = acc;
}

__global__ void k_prepWtu(const float* __restrict__ We)
{
    const float scale = 0.17677669529663687f;
    int t = blockIdx.x * blockDim.x + threadIdx.x;   // LL*4*32*128 = 65536
    if (t >= LL * 4 * 32 * HH) return;
    int l  = t >> 14;
    int r  = t & 16383;
    int h  = r >> 12;
    int r2 = r & 4095;
    int c  = r2 >> 7, j = r2 & 127;
    g_Wtu[t] = We[l * 16384 + j * 128 + h * 32 + c] * scale;
}

// ---------------- fused 4-matrix GEMM (proven) ----------------
#define BM 64
#define BK 16

__global__ void gemm4(const float* __restrict__ A,
                      const float* __restrict__ B0, const float* __restrict__ B1,
                      const float* __restrict__ B2, const float* __restrict__ B3,
                      const float* __restrict__ c0, const float* __restrict__ c1,
                      const float* __restrict__ c2, const float* __restrict__ c3,
                      float* __restrict__ C0, float* __restrict__ C1,
                      float* __restrict__ C2, float* __restrict__ C3)
{
    const float* B    = (blockIdx.y == 0) ? B0 : (blockIdx.y == 1) ? B1 : (blockIdx.y == 2) ? B2 : B3;
    const float* bias = (blockIdx.y == 0) ? c0 : (blockIdx.y == 1) ? c1 : (blockIdx.y == 2) ? c2 : c3;
    float* C          = (blockIdx.y == 0) ? C0 : (blockIdx.y == 1) ? C1 : (blockIdx.y == 2) ? C2 : C3;

    __shared__ float As[BK][BM + 4];
    __shared__ float Bs[BK][128];
    int tid  = threadIdx.x;
    int tcol = tid & 15;
    int trow = tid >> 4;
    int block_m = blockIdx.x * BM;

    float acc[8][8];
#pragma unroll
    for (int i = 0; i < 8; i++)
#pragma unroll
        for (int j = 0; j < 8; j++) acc[i][j] = 0.f;

    for (int k0 = 0; k0 < 128; k0 += BK) {
#pragma unroll
        for (int it = 0; it < 2; it++) {
            int f = tid + it * 128;
            int row = f >> 2;
            int kq  = f & 3;
            float4 a = *(const float4*)&A[(size_t)(block_m + row) * 128 + k0 + kq * 4];
            As[kq * 4 + 0][row] = a.x;
            As[kq * 4 + 1][row] = a.y;
            As[kq * 4 + 2][row] = a.z;
            As[kq * 4 + 3][row] = a.w;
        }
#pragma unroll
        for (int it = 0; it < 4; it++) {
            int f = tid + it * 128;
            int krow = f >> 5;
            int nq   = f & 31;
            *(float4*)&Bs[krow][nq * 4] = *(const float4*)&B[(k0 + krow) * 128 + nq * 4];
        }
        __syncthreads();
#pragma unroll
        for (int k = 0; k < BK; k++) {
            float a[8], b[8];
            *(float4*)&a[0] = *(float4*)&As[k][trow * 4];
            *(float4*)&a[4] = *(float4*)&As[k][32 + trow * 4];
            *(float4*)&b[0] = *(float4*)&Bs[k][tcol * 4];
            *(float4*)&b[4] = *(float4*)&Bs[k][64 + tcol * 4];
#pragma unroll
            for (int i = 0; i < 8; i++)
#pragma unroll
                for (int j = 0; j < 8; j++)
                    acc[i][j] += a[i] * b[j];
        }
        __syncthreads();
    }

    float4 bLo = *(const float4*)&bias[tcol * 4];
    float4 bHi = *(const float4*)&bias[64 + tcol * 4];
#pragma unroll
    for (int i = 0; i < 8; i++) {
        int row = block_m + ((i < 4) ? (trow * 4 + i) : (32 + trow * 4 + i - 4));
        float4 lo, hi;
        lo.x = acc[i][0] + bLo.x; lo.y = acc[i][1] + bLo.y;
        lo.z = acc[i][2] + bLo.z; lo.w = acc[i][3] + bLo.w;
        hi.x = acc[i][4] + bHi.x; hi.y = acc[i][5] + bHi.y;
        hi.z = acc[i][6] + bHi.z; hi.w = acc[i][7] + bHi.w;
        *(float4*)&C[(size_t)row * 128 + tcol * 4]      = lo;
        *(float4*)&C[(size_t)row * 128 + 64 + tcol * 4] = hi;
    }
}

// ---------------- u GEMM: u[n, h*128+j] = sum_c q[n, h*32+c] * Wtu[l,h,c,j] ----------------
// grid (625, 4 heads), 128 threads; tile 64 rows x 128 cols, K=32. A = g_q (already written).
__global__ void gemm_u(const float* __restrict__ q, int l)
{
    __shared__ float As[BK][BM + 4];
    __shared__ float Bs[BK][128];
    int h = blockIdx.y;
    const float* B = g_Wtu + (size_t)(l * 4 + h) * 4096;
    int tid  = threadIdx.x;
    int tcol = tid & 15;
    int trow = tid >> 4;
    int block_m = blockIdx.x * BM;

    float acc[8][8];
#pragma unroll
    for (int i = 0; i < 8; i++)
#pragma unroll
        for (int j = 0; j < 8; j++) acc[i][j] = 0.f;

    for (int k0 = 0; k0 < 32; k0 += BK) {
#pragma unroll
        for (int it = 0; it < 2; it++) {
            int f = tid + it * 128;
            int row = f >> 2;
            int kq  = f & 3;
            float4 a = *(const float4*)&q[(size_t)(block_m + row) * 128 + h * 32 + k0 + kq * 4];
            As[kq * 4 + 0][row] = a.x;
            As[kq * 4 + 1][row] = a.y;
            As[kq * 4 + 2][row] = a.z;
            As[kq * 4 + 3][row] = a.w;
        }
#pragma unroll
        for (int it = 0; it < 4; it++) {
            int f = tid + it * 128;
            int krow = f >> 5;
            int nq   = f & 31;
            *(float4*)&Bs[krow][nq * 4] = *(const float4*)&B[(size_t)(k0 + krow) * 128 + nq * 4];
        }
        __syncthreads();
#pragma unroll
        for (int k = 0; k < BK; k++) {
            float a[8], b[8];
            *(float4*)&a[0] = *(float4*)&As[k][trow * 4];
            *(float4*)&a[4] = *(float4*)&As[k][32 + trow * 4];
            *(float4*)&b[0] = *(float4*)&Bs[k][tcol * 4];
            *(float4*)&b[4] = *(float4*)&Bs[k][64 + tcol * 4];
#pragma unroll
            for (int i = 0; i < 8; i++)
#pragma unroll
                for (int j = 0; j < 8; j++)
                    acc[i][j] += a[i] * b[j];
        }
        __syncthreads();
    }

#pragma unroll
    for (int i = 0; i < 8; i++) {
        int row = block_m + ((i < 4) ? (trow * 4 + i) : (32 + trow * 4 + i - 4));
        float4 lo = make_float4(acc[i][0], acc[i][1], acc[i][2], acc[i][3]);
        float4 hi = make_float4(acc[i][4], acc[i][5], acc[i][6], acc[i][7]);
        *(float4*)&g_u[(size_t)row * 512 + h * 128 + tcol * 4]      = lo;
        *(float4*)&g_u[(size_t)row * 512 + h * 128 + 64 + tcol * 4] = hi;
    }
}

// ---------------- attention (R7 version, proven) ----------------
__global__ void k_attn2(const float* __restrict__ q, const float* __restrict__ kk,
                        const float* __restrict__ vv, const float* __restrict__ sk)
{
    int wrp  = (blockIdx.x * blockDim.x + threadIdx.x) >> 5;
    int lane = threadIdx.x & 31;
    if (wrp >= NN) return;
    int g = lane >> 3;
    const float scale = 0.17677669529663687f;
    const unsigned FULL = 0xffffffffu;

    float4 q4 = *(const float4*)(q + (size_t)wrp * 128 + lane * 4);
    q4.x *= scale; q4.y *= scale; q4.z *= scale; q4.w *= scale;
    float4 u0 = *(const float4*)(g_u + (size_t)wrp * 512 +   0 + lane * 4);
    float4 u1 = *(const float4*)(g_u + (size_t)wrp * 512 + 128 + lane * 4);
    float4 u2 = *(const float4*)(g_u + (size_t)wrp * 512 + 256 + lane * 4);
    float4 u3 = *(const float4*)(g_u + (size_t)wrp * 512 + 384 + lane * 4);

    float s0 = 0.f, s1 = 0.f, s2 = 0.f, s3 = 0.f;
    float4 e0 = make_float4(0.f, 0.f, 0.f, 0.f), e1 = e0, e2 = e0, e3 = e0;
    float4 vacc = e0;

    int beg = g_rowstart[wrp], end = g_rowstart[wrp + 1];
    int idx = beg;

    for (; idx + 1 < end; idx += 2) {
        int sA = g_csrsrc[idx];
        int sB = g_csrsrc[idx + 1];
        float4 eA = *(const float4*)(g_eh + (size_t)idx * 128 + lane * 4);
        float4 eB = *(const float4*)(g_eh + (size_t)(idx + 1) * 128 + lane * 4);
        float4 kA = *(const float4*)(kk + (size_t)sA * 128 + lane * 4);
        float4 kB = *(const float4*)(kk + (size_t)sB * 128 + lane * 4);
        float4 vA = *(const float4*)(vv + (size_t)sA * 128 + lane * 4);
        float4 vB = *(const float4*)(vv + (size_t)sB * 128 + lane * 4);

        float A0 = eA.x * u0.x + eA.y * u0.y + eA.z * u0.z + eA.w * u0.w;
        float A1 = eA.x * u1.x + eA.y * u1.y + eA.z * u1.z + eA.w * u1.w;
        float A2 = eA.x * u2.x + eA.y * u2.y + eA.z * u2.z + eA.w * u2.w;
        float A3 = eA.x * u3.x + eA.y * u3.y + eA.z * u3.z + eA.w * u3.w;
        float B0 = eB.x * u0.x + eB.y * u0.y + eB.z * u0.z + eB.w * u0.w;
        float B1 = eB.x * u1.x + eB.y * u1.y + eB.z * u1.z + eB.w * u1.w;
        float B2 = eB.x * u2.x + eB.y * u2.y + eB.z * u2.z + eB.w * u2.w;
        float B3 = eB.x * u3.x + eB.y * u3.y + eB.z * u3.z + eB.w * u3.w;
        float pA = q4.x * kA.x + q4.y * kA.y + q4.z * kA.z + q4.w * kA.w;
        float pB = q4.x * kB.x + q4.y * kB.y + q4.z * kB.z + q4.w * kB.w;
        A0 += (g == 0) ? pA : 0.f;  B0 += (g == 0) ? pB : 0.f;
        A1 += (g == 1) ? pA : 0.f;  B1 += (g == 1) ? pB : 0.f;
        A2 += (g == 2) ? pA : 0.f;  B2 += (g == 2) ? pB : 0.f;
        A3 += (g == 3) ? pA : 0.f;  B3 += (g == 3) ? pB : 0.f;

        A0 += __shfl_xor_sync(FULL, A0, 16); B0 += __shfl_xor_sync(FULL, B0, 16);
        A1 += __shfl_xor_sync(FULL, A1, 16); B1 += __shfl_xor_sync(FULL, B1, 16);
        A2 += __shfl_xor_sync(FULL, A2, 16); B2 += __shfl_xor_sync(FULL, B2, 16);
        A3 += __shfl_xor_sync(FULL, A3, 16); B3 += __shfl_xor_sync(FULL, B3, 16);
        A0 += __shfl_xor_sync(FULL, A0, 8);  B0 += __shfl_xor_sync(FULL, B0, 8);
        A1 += __shfl_xor_sync(FULL, A1, 8);  B1 += __shfl_xor_sync(FULL, B1, 8);
        A2 += __shfl_xor_sync(FULL, A2, 8);  B2 += __shfl_xor_sync(FULL, B2, 8);
        A3 += __shfl_xor_sync(FULL, A3, 8);  B3 += __shfl_xor_sync(FULL, B3, 8);

        float PA = (g == 0) ? A0 : (g == 1) ? A1 : (g == 2) ? A2 : A3;
        float PB = (g == 0) ? B0 : (g == 1) ? B1 : (g == 2) ? B2 : B3;
        PA += __shfl_xor_sync(FULL, PA, 1);  PB += __shfl_xor_sync(FULL, PB, 1);
        PA += __shfl_xor_sync(FULL, PA, 2);  PB += __shfl_xor_sync(FULL, PB, 2);
        PA += __shfl_xor_sync(FULL, PA, 4);  PB += __shfl_xor_sync(FULL, PB, 4);

        float wA = __expf(PA);
        float wB = __expf(PB);

        float waA = __shfl_xor_sync(FULL, wA, 8);
        float waB = __shfl_xor_sync(FULL, wB, 8);
        float wbA = __shfl_xor_sync(FULL, wA, 16);
        float wbB = __shfl_xor_sync(FULL, wB, 16);
        float wcA = __shfl_xor_sync(FULL, waA, 16);
        float wcB = __shfl_xor_sync(FULL, waB, 16);

        float w0A = (g == 0) ? wA : (g == 1) ? waA : (g == 2) ? wbA : wcA;
        float w1A = (g == 1) ? wA : (g == 0) ? waA : (g == 3) ? wbA : wcA;
        float w2A = (g == 2) ? wA : (g == 3) ? waA : (g == 0) ? wbA : wcA;
        float w3A = (g == 3) ? wA : (g == 2) ? waA : (g == 1) ? wbA : wcA;
        float w0B = (g == 0) ? wB : (g == 1) ? waB : (g == 2) ? wbB : wcB;
        float w1B = (g == 1) ? wB : (g == 0) ? waB : (g == 3) ? wbB : wcB;
        float w2B = (g == 2) ? wB : (g == 3) ? waB : (g == 0) ? wbB : wcB;
        float w3B = (g == 3) ? wB : (g == 2) ? waB : (g == 1) ? wbB : wcB;

        s0 += w0A + w0B; s1 += w1A + w1B; s2 += w2A + w2B; s3 += w3A + w3B;

        e0.x += w0A * eA.x + w0B * eB.x; e0.y += w0A * eA.y + w0B * eB.y;
        e0.z += w0A * eA.z + w0B * eB.z; e0.w += w0A * eA.w + w0B * eB.w;
        e1.x += w1A * eA.x + w1B * eB.x; e1.y += w1A * eA.y + w1B * eB.y;
        e1.z += w1A * eA.z + w1B * eB.z; e1.w += w1A * eA.w + w1B * eB.w;
        e2.x += w2A * eA.x + w2B * eB.x; e2.y += w2A * eA.y + w2B * eB.y;
        e2.z += w2A * eA.z + w2B * eB.z; e2.w += w2A * eA.w + w2B * eB.w;
        e3.x += w3A * eA.x + w3B * eB.x; e3.y += w3A * eA.y + w3B * eB.y;
        e3.z += w3A * eA.z + w3B * eB.z; e3.w += w3A * eA.w + w3B * eB.w;

        vacc.x += wA * vA.x + wB * vB.x;
        vacc.y += wA * vA.y + wB * vB.y;
        vacc.z += wA * vA.z + wB * vB.z;
        vacc.w += wA * vA.w + wB * vB.w;
    }

    if (idx < end) {
        int sA = g_csrsrc[idx];
        float4 eA = *(const float4*)(g_eh + (size_t)idx * 128 + lane * 4);
        float4 kA = *(const float4*)(kk + (size_t)sA * 128 + lane * 4);
        float4 vA = *(const float4*)(vv + (size_t)sA * 128 + lane * 4);

        float A0 = eA.x * u0.x + eA.y * u0.y + eA.z * u0.z + eA.w * u0.w;
        float A1 = eA.x * u1.x + eA.y * u1.y + eA.z * u1.z + eA.w * u1.w;
        float A2 = eA.x * u2.x + eA.y * u2.y + eA.z * u2.z + eA.w * u2.w;
        float A3 = eA.x * u3.x + eA.y * u3.y + eA.z * u3.z + eA.w * u3.w;
        float pA = q4.x * kA.x + q4.y * kA.y + q4.z * kA.z + q4.w * kA.w;
        A0 += (g == 0) ? pA : 0.f;
        A1 += (g == 1) ? pA : 0.f;
        A2 += (g == 2) ? pA : 0.f;
        A3 += (g == 3) ? pA : 0.f;

        A0 += __shfl_xor_sync(FULL, A0, 16);
        A1 += __shfl_xor_sync(FULL, A1, 16);
        A2 += __shfl_xor_sync(FULL, A2, 16);
        A3 += __shfl_xor_sync(FULL, A3, 16);
        A0 += __shfl_xor_sync(FULL, A0, 8);
        A1 += __shfl_xor_sync(FULL, A1, 8);
        A2 += __shfl_xor_sync(FULL, A2, 8);
        A3 += __shfl_xor_sync(FULL, A3, 8);

        float PA = (g == 0) ? A0 : (g == 1) ? A1 : (g == 2) ? A2 : A3;
        PA += __shfl_xor_sync(FULL, PA, 1);
        PA += __shfl_xor_sync(FULL, PA, 2);
        PA += __shfl_xor_sync(FULL, PA, 4);

        float wA = __expf(PA);
        float waA = __shfl_xor_sync(FULL, wA, 8);
        float wbA = __shfl_xor_sync(FULL, wA, 16);
        float wcA = __shfl_xor_sync(FULL, waA, 16);

        float w0A = (g == 0) ? wA : (g == 1) ? waA : (g == 2) ? wbA : wcA;
        float w1A = (g == 1) ? wA : (g == 0) ? waA : (g == 3) ? wbA : wcA;
        float w2A = (g == 2) ? wA : (g == 3) ? waA : (g == 0) ? wbA : wcA;
        float w3A = (g == 3) ? wA : (g == 2) ? waA : (g == 1) ? wbA : wcA;

        s0 += w0A; s1 += w1A; s2 += w2A; s3 += w3A;
        e0.x += w0A * eA.x; e0.y += w0A * eA.y; e0.z += w0A * eA.z; e0.w += w0A * eA.w;
        e1.x += w1A * eA.x; e1.y += w1A * eA.y; e1.z += w1A * eA.z; e1.w += w1A * eA.w;
        e2.x += w2A * eA.x; e2.y += w2A * eA.y; e2.z += w2A * eA.z; e2.w += w2A * eA.w;
        e3.x += w3A * eA.x; e3.y += w3A * eA.y; e3.z += w3A * eA.z; e3.w += w3A * eA.w;
        vacc.x += wA * vA.x; vacc.y += wA * vA.y;
        vacc.z += wA * vA.z; vacc.w += wA * vA.w;
    }

    float sg  = (g == 0) ? s0 : (g == 1) ? s1 : (g == 2) ? s2 : s3;
    float ivg = 1.f / (sg + 1e-16f);
    float4 s4 = *(const float4*)(sk + (size_t)wrp * 128 + lane * 4);
    float4 t;
    t.x = vacc.x * ivg + s4.x;
    t.y = vacc.y * ivg + s4.y;
    t.z = vacc.z * ivg + s4.z;
    t.w = vacc.w * ivg + s4.w;
    *(float4*)(g_tmpv + (size_t)wrp * 128 + lane * 4) = t;

    float i0 = 1.f / (s0 + 1e-16f), i1 = 1.f / (s1 + 1e-16f);
    float i2 = 1.f / (s2 + 1e-16f), i3 = 1.f / (s3 + 1e-16f);
    float4 a;
    a.x = e0.x * i0; a.y = e0.y * i0; a.z = e0.z * i0; a.w = e0.w * i0;
    *(float4*)(g_agg + (size_t)wrp * 512 +   0 + lane * 4) = a;
    a.x = e1.x * i1; a.y = e1.y * i1; a.z = e1.z * i1; a.w = e1.w * i1;
    *(float4*)(g_agg + (size_t)wrp * 512 + 128 + lane * 4) = a;
    a.x = e2.x * i2; a.y = e2.y * i2; a.z = e2.z * i2; a.w = e2.w * i2;
    *(float4*)(g_agg + (size_t)wrp * 512 + 256 + lane * 4) = a;
    a.x = e3.x * i3; a.y = e3.y * i3; a.z = e3.z * i3; a.w = e3.w * i3;
    *(float4*)(g_agg + (size_t)wrp * 512 + 384 + lane * 4) = a;
}

// ---------------- post-GEMM: og[n, h*32+c] = sum_j agg[n, h*128+j] * We[j][h*32+c] --------
__global__ void gemm_p(const float* __restrict__ WeL)
{
    __shared__ float As[16][BM + 4];
    __shared__ float Bs[16][36];
    int h = blockIdx.y;
    int tid  = threadIdx.x;
    int tcol = tid & 7;
    int trow = tid >> 3;
    int block_m = blockIdx.x * BM;

    float acc[4][4];
#pragma unroll
    for (int i = 0; i < 4; i++)
#pragma unroll
        for (int j = 0; j < 4; j++) acc[i][j] = 0.f;

    for (int k0 = 0; k0 < 128; k0 += 16) {
#pragma unroll
        for (int it = 0; it < 2; it++) {
            int f = tid + it * 128;
            int row = f >> 2;
            int kq  = f & 3;
            float4 a = *(const float4*)&g_agg[(size_t)(block_m + row) * 512 + h * 128 + k0 + kq * 4];
            As[kq * 4 + 0][row] = a.x;
            As[kq * 4 + 1][row] = a.y;
            As[kq * 4 + 2][row] = a.z;
            As[kq * 4 + 3][row] = a.w;
        }
        {
            int krow = tid >> 3;
            int c4   = tid & 7;
            float4 b = *(const float4*)&WeL[(size_t)(k0 + krow) * 128 + h * 32 + c4 * 4];
            *(float4*)&Bs[krow][c4 * 4] = b;
        }
        __syncthreads();
#pragma unroll
        for (int k = 0; k < 16; k++) {
            float4 av = *(float4*)&As[k][trow * 4];
            float4 bv = *(float4*)&Bs[k][tcol * 4];
            float a[4] = {av.x, av.y, av.z, av.w};
            float b[4] = {bv.x, bv.y, bv.z, bv.w};
#pragma unroll
            for (int i = 0; i < 4; i++)
#pragma unroll
                for (int j = 0; j < 4; j++)
                    acc[i][j] += a[i] * b[j];
        }
        __syncthreads();
    }

#pragma unroll
    for (int i = 0; i < 4; i++) {
        float4 o = make_float4(acc[i][0], acc[i][1], acc[i][2], acc[i][3]);
        *(float4*)&g_og[(size_t)(block_m + trow * 4 + i) * 128 + h * 32 + tcol * 4] = o;
    }
}

// ---------------- LN + ReLU: hout = relu(LN(tmpv + og)) ----------------
__global__ void k_lnrelu(const float* __restrict__ lng, const float* __restrict__ lnb,
                         float* __restrict__ hout)
{
    int wrp  = (blockIdx.x * blockDim.x + threadIdx.x) >> 5;
    int lane = threadIdx.x & 31;
    if (wrp >= NN) return;

    float4 t = *(const float4*)(g_tmpv + (size_t)wrp * 128 + lane * 4);
    float4 o = *(const float4*)(g_og   + (size_t)wrp * 128 + lane * 4);
    float ox = t.x + o.x, oy = t.y + o.y, oz = t.z + o.z, ow = t.w + o.w;

    float s = ox + oy + oz + ow;
#pragma unroll
    for (int off = 16; off; off >>= 1) s += __shfl_xor_sync(0xffffffffu, s, off);
    float mu = s * 0.0078125f;
    float dx = ox - mu, dy = oy - mu, dz = oz - mu, dw = ow - mu;
    float sq = dx * dx + dy * dy + dz * dz + dw * dw;
#pragma unroll
    for (int off = 16; off; off >>= 1) sq += __shfl_xor_sync(0xffffffffu, sq, off);
    float r = rsqrtf(sq * 0.0078125f + 1e-5f);

    float4 g4 = *(const float4*)&lng[lane * 4];
    float4 b4 = *(const float4*)&lnb[lane * 4];
    float4 res;
    res.x = fmaxf(0.f, dx * r * g4.x + b4.x);
    res.y = fmaxf(0.f, dy * r * g4.y + b4.y);
    res.z = fmaxf(0.f, dz * r * g4.z + b4.z);
    res.w = fmaxf(0.f, dw * r * g4.w + b4.w);
    *(float4*)(hout + (size_t)wrp * 128 + lane * 4) = res;
}

// ---------------- global mean pool + MLP heads ----------------
__global__ void k_pool(const float* __restrict__ h, const int* __restrict__ batch)
{
    int t = blockIdx.x * blockDim.x + threadIdx.x;
    if (t >= NN * HH) return;
    int n = t >> 7, c = t & 127;
    int b = batch[n];
    atomicAdd(&g_pool[b * HH + c], h[t]);
    if (c == 0) atomicAdd(&g_pcnt[b], 1.f);
}

__global__ void k_heads(const float* __restrict__ dw1, const float* __restrict__ db1,
                        const float* __restrict__ dw2, const float* __restrict__ db2,
                        const float* __restrict__ tw1, const float* __restrict__ tb1,
                        const float* __restrict__ tw2, const float* __restrict__ tb2,
                        float* __restrict__ out)
{
    const float* W1 = blockIdx.x ? tw1 : dw1;
    const float* B1 = blockIdx.x ? tb1 : db1;
    const float* W2 = blockIdx.x ? tw2 : dw2;
    const float* B2 = blockIdx.x ? tb2 : db2;

    __shared__ float hg[GG][HH];
    __shared__ float t1[GG][64];
    int t = threadIdx.x;

    for (int i = t; i < GG * HH; i += 256) {
        int g = i >> 7;
        hg[g][i & 127] = g_pool[i] / fmaxf(g_pcnt[g], 1.f);
    }
    __syncthreads();
    for (int i = t; i < GG * 64; i += 256) {
        int g = i >> 6, j = i & 63;
        float acc = B1[j];
        for (int c = 0; c < 128; c++) acc += hg[g][c] * W1[c * 64 + j];
        t1[g][j] = fmaxf(acc, 0.f);
    }
    __syncthreads();
    for (int i = t; i < GG * OO; i += 256) {
        int g = i / OO, o = i % OO;
        float acc = B2[o];
        for (int j = 0; j < 64; j++) acc += t1[g][j] * W2[j * OO + o];
        out[blockIdx.x * GG * OO + i] = acc;
    }
}

// ---------------- launch ----------------
extern "C" void kernel_launch(void* const* d_in, const int* in_sizes, int n_in,
                              void* d_out, int out_size)
{
    const float* x      = (const float*)d_in[0];
    const float* eattr  = (const float*)d_in[1];
    const float* node_w = (const float*)d_in[2];
    const float* node_b = (const float*)d_in[3];
    const float* edge_w = (const float*)d_in[4];
    const float* edge_b = (const float*)d_in[5];
    const float* Wq  = (const float*)d_in[6];
    const float* bq  = (const float*)d_in[7];
    const float* Wk  = (const float*)d_in[8];
    const float* bk  = (const float*)d_in[9];
    const float* Wv  = (const float*)d_in[10];
    const float* bv  = (const float*)d_in[11];
    const float* We  = (const float*)d_in[12];
    const float* Wsk = (const float*)d_in[13];
    const float* bsk = (const float*)d_in[14];
    const float* lng = (const float*)d_in[15];
    const float* lnb = (const float*)d_in[16];
    const float* dw1 = (const float*)d_in[17];
    const float* db1 = (const float*)d_in[18];
    const float* dw2 = (const float*)d_in[19];
    const float* db2 = (const float*)d_in[20];
    const float* tw1 = (const float*)d_in[21];
    const float* tb1 = (const float*)d_in[22];
    const float* tw2 = (const float*)d_in[23];
    const float* tb2 = (const float*)d_in[24];
    const int*   ei    = (const int*)d_in[25];
    const int*   batch = (const int*)d_in[26];
    float* out = (float*)d_out;

    float *hA, *hB, *qp, *kp, *vp, *sp;
    cudaGetSymbolAddress((void**)&hA, g_hA);
    cudaGetSymbolAddress((void**)&hB, g_hB);
    cudaGetSymbolAddress((void**)&qp, g_q);
    cudaGetSymbolAddress((void**)&kp, g_k);
    cudaGetSymbolAddress((void**)&vp, g_v);
    cudaGetSymbolAddress((void**)&sp, g_s);

    dim3 gg(NN / BM, 4);
    dim3 gp(NN / BM, 4);

    // gemm4 (layer 0) lands in the ncu-profiled slot (#4).
    k_zero<<<(NN + 255) / 256, 256>>>();
    k_prepWtu<<<(LL * 4 * 32 * HH + 255) / 256, 256>>>(We);
    k_nodeproj<<<(NN * HH + 255) / 256, 256>>>(x, node_w, node_b);
    gemm4<<<gg, 128>>>(hA, Wq, Wk, Wv, Wsk, bq, bk, bv, bsk, qp, kp, vp, sp);
    gemm_u<<<gp, 128>>>(qp, 0);
    k_hist<<<(EE + 255) / 256, 256>>>(ei);
    k_scan<<<1, 1024>>>();
    k_scatter<<<(EE + 255) / 256, 256>>>(ei);
    k_edgeproj<<<(EE * HH + 255) / 256, 256>>>(eattr, edge_w, edge_b);

    float* hcur = hA;
    float* hnxt = hB;
    for (int i = 0; i < LL; i++) {
        if (i > 0) {
            gemm4<<<gg, 128>>>(hcur,
                               Wq + i * HH * HH, Wk + i * HH * HH,
                               Wv + i * HH * HH, Wsk + i * HH * HH,
                               bq + i * HH, bk + i * HH, bv + i * HH, bsk + i * HH,
                               qp, kp, vp, sp);
            gemm_u<<<gp, 128>>>(qp, i);
        }
        k_attn2<<<(NN * 32) / 256, 256>>>(qp, kp, vp, sp);
        gemm_p<<<gp, 128>>>(We + i * HH * HH);
        k_lnrelu<<<(NN * 32) / 256, 256>>>(lng + i * HH, lnb + i * HH, hnxt);
        float* tmp = hcur; hcur = hnxt; hnxt = tmp;
    }

    k_pool<<<(NN * HH + 255) / 256, 256>>>(hcur, batch);
    k_heads<<<2, 256>>>(dw1, db1, dw2, db2, tw1, tb1, tw2, tb2, out);
}

// round 10
// speedup vs baseline: 1.2216x; 1.0085x over previous
#include <cuda_runtime.h>
#include <math.h>

#define NN 40000
#define EE 640000
#define GG 32
#define HH 128
#define LL 4
#define OO 100

// ---------------- device scratch ----------------
__device__ float g_hA[NN * HH];
__device__ float g_hB[NN * HH];
__device__ float g_eh[EE * HH];       // edge projection, CSR-permuted order
__device__ float g_q [NN * HH];
__device__ float g_k [NN * HH];
__device__ float g_v [NN * HH];
__device__ float g_s [NN * HH];
__device__ float g_u  [NN * 512];
__device__ float g_agg[NN * 512];
__device__ float g_tmpv[NN * HH];
__device__ float g_og [NN * HH];          // agg @ We (post-GEMM result)
__device__ float g_Wtu[LL * 4 * 32 * HH]; // Wtu[l,h,c,j] = scale * We[l][j][h*32+c]
__device__ int   g_hist[NN];
__device__ int   g_rowstart[NN + 1];
__device__ int   g_cursor[NN];
__device__ int   g_edgepos[EE];
__device__ int   g_csrsrc[EE];
__device__ float g_pool[GG * HH];
__device__ float g_pcnt[GG];

// ---------------- CSR construction ----------------
__global__ void k_zero()
{
    int i = blockIdx.x * blockDim.x + threadIdx.x;
    if (i < NN) g_hist[i] = 0;
    if (i < GG * HH) g_pool[i] = 0.f;
    if (i < GG) g_pcnt[i] = 0.f;
}

__global__ void k_hist(const int* __restrict__ ei)
{
    int e = blockIdx.x * blockDim.x + threadIdx.x;
    if (e < EE) atomicAdd(&g_hist[ei[EE + e]], 1);
}

__global__ void k_scan()
{
    const int T = 1024, CH = 40;
    __shared__ int sh[T];
    int t = threadIdx.x;
    int base = t * CH;
    int loc[CH];
    int run = 0;
#pragma unroll
    for (int i = 0; i < CH; i++) {
        int idx = base + i;
        int vv = (idx < NN) ? g_hist[idx] : 0;
        loc[i] = run;
        run += vv;
    }
    sh[t] = run;
    __syncthreads();
    for (int off = 1; off < T; off <<= 1) {
        int vv = (t >= off) ? sh[t - off] : 0;
        __syncthreads();
        sh[t] += vv;
        __syncthreads();
    }
    int offset = (t > 0) ? sh[t - 1] : 0;
#pragma unroll
    for (int i = 0; i < CH; i++) {
        int idx = base + i;
        if (idx < NN) {
            int p = offset + loc[i];
            g_rowstart[idx] = p;
            g_cursor[idx]   = p;
        }
    }
    if (t == T - 1) g_rowstart[NN] = sh[T - 1];
}

__global__ void k_scatter(const int* __restrict__ ei)
{
    int e = blockIdx.x * blockDim.x + threadIdx.x;
    if (e < EE) {
        int dst = ei[EE + e];
        int pos = atomicAdd(&g_cursor[dst], 1);
        g_edgepos[e] = pos;
        g_csrsrc[pos] = ei[e];
    }
}

// ---------------- input projections / weight prep ----------------
__global__ void k_nodeproj(const float* __restrict__ x,
                           const float* __restrict__ w,
                           const float* __restrict__ b)
{
    int t = blockIdx.x * blockDim.x + threadIdx.x;
    if (t >= NN * HH) return;
    int n = t >> 7, c = t & 127;
    const float* xr = x + n * 4;
    float acc = b[c];
    acc += xr[0] * w[c] + xr[1] * w[128 + c] + xr[2] * w[256 + c] + xr[3] * w[384 + c];
    g_hA[t] = acc;
}

__global__ void k_edgeproj(const float* __restrict__ ea,
                           const float* __restrict__ w,
                           const float* __restrict__ b)
{
    int t = blockIdx.x * blockDim.x + threadIdx.x;
    if (t >= EE * HH) return;
    int e = t >> 7, c = t & 127;
    const float* ar = ea + e * 5;
    float acc = b[c];
#pragma unroll
    for (int j = 0; j < 5; j++) acc += ar[j] * w[j * 128 + c];
    int pos = g_edgepos[e];
    g_eh[pos * HH + c] = acc;
}

__global__ void k_prepWtu(const float* __restrict__ We)
{
    const float scale = 0.17677669529663687f;
    int t = blockIdx.x * blockDim.x + threadIdx.x;   // LL*4*32*128 = 65536
    if (t >= LL * 4 * 32 * HH) return;
    int l  = t >> 14;
    int r  = t & 16383;
    int h  = r >> 12;
    int r2 = r & 4095;
    int c  = r2 >> 7, j = r2 & 127;
    g_Wtu[t] = We[l * 16384 + j * 128 + h * 32 + c] * scale;
}

// ---------------- fused 4-matrix GEMM (proven) ----------------
#define BM 64
#define BK 16

__global__ void gemm4(const float* __restrict__ A,
                      const float* __restrict__ B0, const float* __restrict__ B1,
                      const float* __restrict__ B2, const float* __restrict__ B3,
                      const float* __restrict__ c0, const float* __restrict__ c1,
                      const float* __restrict__ c2, const float* __restrict__ c3,
                      float* __restrict__ C0, float* __restrict__ C1,
                      float* __restrict__ C2, float* __restrict__ C3)
{
    const float* B    = (blockIdx.y == 0) ? B0 : (blockIdx.y == 1) ? B1 : (blockIdx.y == 2) ? B2 : B3;
    const float* bias = (blockIdx.y == 0) ? c0 : (blockIdx.y == 1) ? c1 : (blockIdx.y == 2) ? c2 : c3;
    float* C          = (blockIdx.y == 0) ? C0 : (blockIdx.y == 1) ? C1 : (blockIdx.y == 2) ? C2 : C3;

    __shared__ float As[BK][BM + 4];
    __shared__ float Bs[BK][128];
    int tid  = threadIdx.x;
    int tcol = tid & 15;
    int trow = tid >> 4;
    int block_m = blockIdx.x * BM;

    float acc[8][8];
#pragma unroll
    for (int i = 0; i < 8; i++)
#pragma unroll
        for (int j = 0; j < 8; j++) acc[i][j] = 0.f;

    for (int k0 = 0; k0 < 128; k0 += BK) {
#pragma unroll
        for (int it = 0; it < 2; it++) {
            int f = tid + it * 128;
            int row = f >> 2;
            int kq  = f & 3;
            float4 a = *(const float4*)&A[(size_t)(block_m + row) * 128 + k0 + kq * 4];
            As[kq * 4 + 0][row] = a.x;
            As[kq * 4 + 1][row] = a.y;
            As[kq * 4 + 2][row] = a.z;
            As[kq * 4 + 3][row] = a.w;
        }
#pragma unroll
        for (int it = 0; it < 4; it++) {
            int f = tid + it * 128;
            int krow = f >> 5;
            int nq   = f & 31;
            *(float4*)&Bs[krow][nq * 4] = *(const float4*)&B[(k0 + krow) * 128 + nq * 4];
        }
        __syncthreads();
#pragma unroll
        for (int k = 0; k < BK; k++) {
            float a[8], b[8];
            *(float4*)&a[0] = *(float4*)&As[k][trow * 4];
            *(float4*)&a[4] = *(float4*)&As[k][32 + trow * 4];
            *(float4*)&b[0] = *(float4*)&Bs[k][tcol * 4];
            *(float4*)&b[4] = *(float4*)&Bs[k][64 + tcol * 4];
#pragma unroll
            for (int i = 0; i < 8; i++)
#pragma unroll
                for (int j = 0; j < 8; j++)
                    acc[i][j] += a[i] * b[j];
        }
        __syncthreads();
    }

    float4 bLo = *(const float4*)&bias[tcol * 4];
    float4 bHi = *(const float4*)&bias[64 + tcol * 4];
#pragma unroll
    for (int i = 0; i < 8; i++) {
        int row = block_m + ((i < 4) ? (trow * 4 + i) : (32 + trow * 4 + i - 4));
        float4 lo, hi;
        lo.x = acc[i][0] + bLo.x; lo.y = acc[i][1] + bLo.y;
        lo.z = acc[i][2] + bLo.z; lo.w = acc[i][3] + bLo.w;
        hi.x = acc[i][4] + bHi.x; hi.y = acc[i][5] + bHi.y;
        hi.z = acc[i][6] + bHi.z; hi.w = acc[i][7] + bHi.w;
        *(float4*)&C[(size_t)row * 128 + tcol * 4]      = lo;
        *(float4*)&C[(size_t)row * 128 + 64 + tcol * 4] = hi;
    }
}

// ---------------- u GEMM: u[n, h*128+j] = sum_c q[n, h*32+c] * Wtu[l,h,c,j] ----------------
// grid (625, 4 heads), 128 threads; tile 64 rows x 128 cols, K=32. A = g_q (already written).
__global__ void gemm_u(const float* __restrict__ q, int l)
{
    __shared__ float As[BK][BM + 4];
    __shared__ float Bs[BK][128];
    int h = blockIdx.y;
    const float* B = g_Wtu + (size_t)(l * 4 + h) * 4096;
    int tid  = threadIdx.x;
    int tcol = tid & 15;
    int trow = tid >> 4;
    int block_m = blockIdx.x * BM;

    float acc[8][8];
#pragma unroll
    for (int i = 0; i < 8; i++)
#pragma unroll
        for (int j = 0; j < 8; j++) acc[i][j] = 0.f;

    for (int k0 = 0; k0 < 32; k0 += BK) {
#pragma unroll
        for (int it = 0; it < 2; it++) {
            int f = tid + it * 128;
            int row = f >> 2;
            int kq  = f & 3;
            float4 a = *(const float4*)&q[(size_t)(block_m + row) * 128 + h * 32 + k0 + kq * 4];
            As[kq * 4 + 0][row] = a.x;
            As[kq * 4 + 1][row] = a.y;
            As[kq * 4 + 2][row] = a.z;
            As[kq * 4 + 3][row] = a.w;
        }
#pragma unroll
        for (int it = 0; it < 4; it++) {
            int f = tid + it * 128;
            int krow = f >> 5;
            int nq   = f & 31;
            *(float4*)&Bs[krow][nq * 4] = *(const float4*)&B[(size_t)(k0 + krow) * 128 + nq * 4];
        }
        __syncthreads();
#pragma unroll
        for (int k = 0; k < BK; k++) {
            float a[8], b[8];
            *(float4*)&a[0] = *(float4*)&As[k][trow * 4];
            *(float4*)&a[4] = *(float4*)&As[k][32 + trow * 4];
            *(float4*)&b[0] = *(float4*)&Bs[k][tcol * 4];
            *(float4*)&b[4] = *(float4*)&Bs[k][64 + tcol * 4];
#pragma unroll
            for (int i = 0; i < 8; i++)
#pragma unroll
                for (int j = 0; j < 8; j++)
                    acc[i][j] += a[i] * b[j];
        }
        __syncthreads();
    }

#pragma unroll
    for (int i = 0; i < 8; i++) {
        int row = block_m + ((i < 4) ? (trow * 4 + i) : (32 + trow * 4 + i - 4));
        float4 lo = make_float4(acc[i][0], acc[i][1], acc[i][2], acc[i][3]);
        float4 hi = make_float4(acc[i][4], acc[i][5], acc[i][6], acc[i][7]);
        *(float4*)&g_u[(size_t)row * 512 + h * 128 + tcol * 4]      = lo;
        *(float4*)&g_u[(size_t)row * 512 + h * 128 + 64 + tcol * 4] = hi;
    }
}

// ---------------- attention (R7 version, proven) ----------------
__global__ void k_attn2(const float* __restrict__ q, const float* __restrict__ kk,
                        const float* __restrict__ vv, const float* __restrict__ sk)
{
    int wrp  = (blockIdx.x * blockDim.x + threadIdx.x) >> 5;
    int lane = threadIdx.x & 31;
    if (wrp >= NN) return;
    int g = lane >> 3;
    const float scale = 0.17677669529663687f;
    const unsigned FULL = 0xffffffffu;

    float4 q4 = *(const float4*)(q + (size_t)wrp * 128 + lane * 4);
    q4.x *= scale; q4.y *= scale; q4.z *= scale; q4.w *= scale;
    float4 u0 = *(const float4*)(g_u + (size_t)wrp * 512 +   0 + lane * 4);
    float4 u1 = *(const float4*)(g_u + (size_t)wrp * 512 + 128 + lane * 4);
    float4 u2 = *(const float4*)(g_u + (size_t)wrp * 512 + 256 + lane * 4);
    float4 u3 = *(const float4*)(g_u + (size_t)wrp * 512 + 384 + lane * 4);

    float s0 = 0.f, s1 = 0.f, s2 = 0.f, s3 = 0.f;
    float4 e0 = make_float4(0.f, 0.f, 0.f, 0.f), e1 = e0, e2 = e0, e3 = e0;
    float4 vacc = e0;

    int beg = g_rowstart[wrp], end = g_rowstart[wrp + 1];
    int idx = beg;

    for (; idx + 1 < end; idx += 2) {
        int sA = g_csrsrc[idx];
        int sB = g_csrsrc[idx + 1];
        float4 eA = *(const float4*)(g_eh + (size_t)idx * 128 + lane * 4);
        float4 eB = *(const float4*)(g_eh + (size_t)(idx + 1) * 128 + lane * 4);
        float4 kA = *(const float4*)(kk + (size_t)sA * 128 + lane * 4);
        float4 kB = *(const float4*)(kk + (size_t)sB * 128 + lane * 4);
        float4 vA = *(const float4*)(vv + (size_t)sA * 128 + lane * 4);
        float4 vB = *(const float4*)(vv + (size_t)sB * 128 + lane * 4);

        float A0 = eA.x * u0.x + eA.y * u0.y + eA.z * u0.z + eA.w * u0.w;
        float A1 = eA.x * u1.x + eA.y * u1.y + eA.z * u1.z + eA.w * u1.w;
        float A2 = eA.x * u2.x + eA.y * u2.y + eA.z * u2.z + eA.w * u2.w;
        float A3 = eA.x * u3.x + eA.y * u3.y + eA.z * u3.z + eA.w * u3.w;
        float B0 = eB.x * u0.x + eB.y * u0.y + eB.z * u0.z + eB.w * u0.w;
        float B1 = eB.x * u1.x + eB.y * u1.y + eB.z * u1.z + eB.w * u1.w;
        float B2 = eB.x * u2.x + eB.y * u2.y + eB.z * u2.z + eB.w * u2.w;
        float B3 = eB.x * u3.x + eB.y * u3.y + eB.z * u3.z + eB.w * u3.w;
        float pA = q4.x * kA.x + q4.y * kA.y + q4.z * kA.z + q4.w * kA.w;
        float pB = q4.x * kB.x + q4.y * kB.y + q4.z * kB.z + q4.w * kB.w;
        A0 += (g == 0) ? pA : 0.f;  B0 += (g == 0) ? pB : 0.f;
        A1 += (g == 1) ? pA : 0.f;  B1 += (g == 1) ? pB : 0.f;
        A2 += (g == 2) ? pA : 0.f;  B2 += (g == 2) ? pB : 0.f;
        A3 += (g == 3) ? pA : 0.f;  B3 += (g == 3) ? pB : 0.f;

        A0 += __shfl_xor_sync(FULL, A0, 16); B0 += __shfl_xor_sync(FULL, B0, 16);
        A1 += __shfl_xor_sync(FULL, A1, 16); B1 += __shfl_xor_sync(FULL, B1, 16);
        A2 += __shfl_xor_sync(FULL, A2, 16); B2 += __shfl_xor_sync(FULL, B2, 16);
        A3 += __shfl_xor_sync(FULL, A3, 16); B3 += __shfl_xor_sync(FULL, B3, 16);
        A0 += __shfl_xor_sync(FULL, A0, 8);  B0 += __shfl_xor_sync(FULL, B0, 8);
        A1 += __shfl_xor_sync(FULL, A1, 8);  B1 += __shfl_xor_sync(FULL, B1, 8);
        A2 += __shfl_xor_sync(FULL, A2, 8);  B2 += __shfl_xor_sync(FULL, B2, 8);
        A3 += __shfl_xor_sync(FULL, A3, 8);  B3 += __shfl_xor_sync(FULL, B3, 8);

        float PA = (g == 0) ? A0 : (g == 1) ? A1 : (g == 2) ? A2 : A3;
        float PB = (g == 0) ? B0 : (g == 1) ? B1 : (g == 2) ? B2 : B3;
        PA += __shfl_xor_sync(FULL, PA, 1);  PB += __shfl_xor_sync(FULL, PB, 1);
        PA += __shfl_xor_sync(FULL, PA, 2);  PB += __shfl_xor_sync(FULL, PB, 2);
        PA += __shfl_xor_sync(FULL, PA, 4);  PB += __shfl_xor_sync(FULL, PB, 4);

        float wA = __expf(PA);
        float wB = __expf(PB);

        float waA = __shfl_xor_sync(FULL, wA, 8);
        float waB = __shfl_xor_sync(FULL, wB, 8);
        float wbA = __shfl_xor_sync(FULL, wA, 16);
        float wbB = __shfl_xor_sync(FULL, wB, 16);
        float wcA = __shfl_xor_sync(FULL, waA, 16);
        float wcB = __shfl_xor_sync(FULL, waB, 16);

        float w0A = (g == 0) ? wA : (g == 1) ? waA : (g == 2) ? wbA : wcA;
        float w1A = (g == 1) ? wA : (g == 0) ? waA : (g == 3) ? wbA : wcA;
        float w2A = (g == 2) ? wA : (g == 3) ? waA : (g == 0) ? wbA : wcA;
        float w3A = (g == 3) ? wA : (g == 2) ? waA : (g == 1) ? wbA : wcA;
        float w0B = (g == 0) ? wB : (g == 1) ? waB : (g == 2) ? wbB : wcB;
        float w1B = (g == 1) ? wB : (g == 0) ? waB : (g == 3) ? wbB : wcB;
        float w2B = (g == 2) ? wB : (g == 3) ? waB : (g == 0) ? wbB : wcB;
        float w3B = (g == 3) ? wB : (g == 2) ? waB : (g == 1) ? wbB : wcB;

        s0 += w0A + w0B; s1 += w1A + w1B; s2 += w2A + w2B; s3 += w3A + w3B;

        e0.x += w0A * eA.x + w0B * eB.x; e0.y += w0A * eA.y + w0B * eB.y;
        e0.z += w0A * eA.z + w0B * eB.z; e0.w += w0A * eA.w + w0B * eB.w;
        e1.x += w1A * eA.x + w1B * eB.x; e1.y += w1A * eA.y + w1B * eB.y;
        e1.z += w1A * eA.z + w1B * eB.z; e1.w += w1A * eA.w + w1B * eB.w;
        e2.x += w2A * eA.x + w2B * eB.x; e2.y += w2A * eA.y + w2B * eB.y;
        e2.z += w2A * eA.z + w2B * eB.z; e2.w += w2A * eA.w + w2B * eB.w;
        e3.x += w3A * eA.x + w3B * eB.x; e3.y += w3A * eA.y + w3B * eB.y;
        e3.z += w3A * eA.z + w3B * eB.z; e3.w += w3A * eA.w + w3B * eB.w;

        vacc.x += wA * vA.x + wB * vB.x;
        vacc.y += wA * vA.y + wB * vB.y;
        vacc.z += wA * vA.z + wB * vB.z;
        vacc.w += wA * vA.w + wB * vB.w;
    }

    if (idx < end) {
        int sA = g_csrsrc[idx];
        float4 eA = *(const float4*)(g_eh + (size_t)idx * 128 + lane * 4);
        float4 kA = *(const float4*)(kk + (size_t)sA * 128 + lane * 4);
        float4 vA = *(const float4*)(vv + (size_t)sA * 128 + lane * 4);

        float A0 = eA.x * u0.x + eA.y * u0.y + eA.z * u0.z + eA.w * u0.w;
        float A1 = eA.x * u1.x + eA.y * u1.y + eA.z * u1.z + eA.w * u1.w;
        float A2 = eA.x * u2.x + eA.y * u2.y + eA.z * u2.z + eA.w * u2.w;
        float A3 = eA.x * u3.x + eA.y * u3.y + eA.z * u3.z + eA.w * u3.w;
        float pA = q4.x * kA.x + q4.y * kA.y + q4.z * kA.z + q4.w * kA.w;
        A0 += (g == 0) ? pA : 0.f;
        A1 += (g == 1) ? pA : 0.f;
        A2 += (g == 2) ? pA : 0.f;
        A3 += (g == 3) ? pA : 0.f;

        A0 += __shfl_xor_sync(FULL, A0, 16);
        A1 += __shfl_xor_sync(FULL, A1, 16);
        A2 += __shfl_xor_sync(FULL, A2, 16);
        A3 += __shfl_xor_sync(FULL, A3, 16);
        A0 += __shfl_xor_sync(FULL, A0, 8);
        A1 += __shfl_xor_sync(FULL, A1, 8);
        A2 += __shfl_xor_sync(FULL, A2, 8);
        A3 += __shfl_xor_sync(FULL, A3, 8);

        float PA = (g == 0) ? A0 : (g == 1) ? A1 : (g == 2) ? A2 : A3;
        PA += __shfl_xor_sync(FULL, PA, 1);
        PA += __shfl_xor_sync(FULL, PA, 2);
        PA += __shfl_xor_sync(FULL, PA, 4);

        float wA = __expf(PA);
        float waA = __shfl_xor_sync(FULL, wA, 8);
        float wbA = __shfl_xor_sync(FULL, wA, 16);
        float wcA = __shfl_xor_sync(FULL, waA, 16);

        float w0A = (g == 0) ? wA : (g == 1) ? waA : (g == 2) ? wbA : wcA;
        float w1A = (g == 1) ? wA : (g == 0) ? waA : (g == 3) ? wbA : wcA;
        float w2A = (g == 2) ? wA : (g == 3) ? waA : (g == 0) ? wbA : wcA;
        float w3A = (g == 3) ? wA : (g == 2) ? waA : (g == 1) ? wbA : wcA;

        s0 += w0A; s1 += w1A; s2 += w2A; s3 += w3A;
        e0.x += w0A * eA.x; e0.y += w0A * eA.y; e0.z += w0A * eA.z; e0.w += w0A * eA.w;
        e1.x += w1A * eA.x; e1.y += w1A * eA.y; e1.z += w1A * eA.z; e1.w += w1A * eA.w;
        e2.x += w2A * eA.x; e2.y += w2A * eA.y; e2.z += w2A * eA.z; e2.w += w2A * eA.w;
        e3.x += w3A * eA.x; e3.y += w3A * eA.y; e3.z += w3A * eA.z; e3.w += w3A * eA.w;
        vacc.x += wA * vA.x; vacc.y += wA * vA.y;
        vacc.z += wA * vA.z; vacc.w += wA * vA.w;
    }

    float sg  = (g == 0) ? s0 : (g == 1) ? s1 : (g == 2) ? s2 : s3;
    float ivg = 1.f / (sg + 1e-16f);
    float4 s4 = *(const float4*)(sk + (size_t)wrp * 128 + lane * 4);
    float4 t;
    t.x = vacc.x * ivg + s4.x;
    t.y = vacc.y * ivg + s4.y;
    t.z = vacc.z * ivg + s4.z;
    t.w = vacc.w * ivg + s4.w;
    *(float4*)(g_tmpv + (size_t)wrp * 128 + lane * 4) = t;

    float i0 = 1.f / (s0 + 1e-16f), i1 = 1.f / (s1 + 1e-16f);
    float i2 = 1.f / (s2 + 1e-16f), i3 = 1.f / (s3 + 1e-16f);
    float4 a;
    a.x = e0.x * i0; a.y = e0.y * i0; a.z = e0.z * i0; a.w = e0.w * i0;
    *(float4*)(g_agg + (size_t)wrp * 512 +   0 + lane * 4) = a;
    a.x = e1.x * i1; a.y = e1.y * i1; a.z = e1.z * i1; a.w = e1.w * i1;
    *(float4*)(g_agg + (size_t)wrp * 512 + 128 + lane * 4) = a;
    a.x = e2.x * i2; a.y = e2.y * i2; a.z = e2.z * i2; a.w = e2.w * i2;
    *(float4*)(g_agg + (size_t)wrp * 512 + 256 + lane * 4) = a;
    a.x = e3.x * i3; a.y = e3.y * i3; a.z = e3.z * i3; a.w = e3.w * i3;
    *(float4*)(g_agg + (size_t)wrp * 512 + 384 + lane * 4) = a;
}

// ---------------- post-GEMM: og[n, h*32+c] = sum_j agg[n, h*128+j] * We[j][h*32+c] --------
__global__ void gemm_p(const float* __restrict__ WeL)
{
    __shared__ float As[16][BM + 4];
    __shared__ float Bs[16][36];
    int h = blockIdx.y;
    int tid  = threadIdx.x;
    int tcol = tid & 7;
    int trow = tid >> 3;
    int block_m = blockIdx.x * BM;

    float acc[4][4];
#pragma unroll
    for (int i = 0; i < 4; i++)
#pragma unroll
        for (int j = 0; j < 4; j++) acc[i][j] = 0.f;

    for (int k0 = 0; k0 < 128; k0 += 16) {
#pragma unroll
        for (int it = 0; it < 2; it++) {
            int f = tid + it * 128;
            int row = f >> 2;
            int kq  = f & 3;
            float4 a = *(const float4*)&g_agg[(size_t)(block_m + row) * 512 + h * 128 + k0 + kq * 4];
            As[kq * 4 + 0][row] = a.x;
            As[kq * 4 + 1][row] = a.y;
            As[kq * 4 + 2][row] = a.z;
            As[kq * 4 + 3][row] = a.w;
        }
        {
            int krow = tid >> 3;
            int c4   = tid & 7;
            float4 b = *(const float4*)&WeL[(size_t)(k0 + krow) * 128 + h * 32 + c4 * 4];
            *(float4*)&Bs[krow][c4 * 4] = b;
        }
        __syncthreads();
#pragma unroll
        for (int k = 0; k < 16; k++) {
            float4 av = *(float4*)&As[k][trow * 4];
            float4 bv = *(float4*)&Bs[k][tcol * 4];
            float a[4] = {av.x, av.y, av.z, av.w};
            float b[4] = {bv.x, bv.y, bv.z, bv.w};
#pragma unroll
            for (int i = 0; i < 4; i++)
#pragma unroll
                for (int j = 0; j < 4; j++)
                    acc[i][j] += a[i] * b[j];
        }
        __syncthreads();
    }

#pragma unroll
    for (int i = 0; i < 4; i++) {
        float4 o = make_float4(acc[i][0], acc[i][1], acc[i][2], acc[i][3]);
        *(float4*)&g_og[(size_t)(block_m + trow * 4 + i) * 128 + h * 32 + tcol * 4] = o;
    }
}

// ---------------- LN + ReLU: hout = relu(LN(tmpv + og)) ----------------
__global__ void k_lnrelu(const float* __restrict__ lng, const float* __restrict__ lnb,
                         float* __restrict__ hout)
{
    int wrp  = (blockIdx.x * blockDim.x + threadIdx.x) >> 5;
    int lane = threadIdx.x & 31;
    if (wrp >= NN) return;

    float4 t = *(const float4*)(g_tmpv + (size_t)wrp * 128 + lane * 4);
    float4 o = *(const float4*)(g_og   + (size_t)wrp * 128 + lane * 4);
    float ox = t.x + o.x, oy = t.y + o.y, oz = t.z + o.z, ow = t.w + o.w;

    float s = ox + oy + oz + ow;
#pragma unroll
    for (int off = 16; off; off >>= 1) s += __shfl_xor_sync(0xffffffffu, s, off);
    float mu = s * 0.0078125f;
    float dx = ox - mu, dy = oy - mu, dz = oz - mu, dw = ow - mu;
    float sq = dx * dx + dy * dy + dz * dz + dw * dw;
#pragma unroll
    for (int off = 16; off; off >>= 1) sq += __shfl_xor_sync(0xffffffffu, sq, off);
    float r = rsqrtf(sq * 0.0078125f + 1e-5f);

    float4 g4 = *(const float4*)&lng[lane * 4];
    float4 b4 = *(const float4*)&lnb[lane * 4];
    float4 res;
    res.x = fmaxf(0.f, dx * r * g4.x + b4.x);
    res.y = fmaxf(0.f, dy * r * g4.y + b4.y);
    res.z = fmaxf(0.f, dz * r * g4.z + b4.z);
    res.w = fmaxf(0.f, dw * r * g4.w + b4.w);
    *(float4*)(hout + (size_t)wrp * 128 + lane * 4) = res;
}

// ---------------- global mean pool + MLP heads ----------------
__global__ void k_pool(const float* __restrict__ h, const int* __restrict__ batch)
{
    int t = blockIdx.x * blockDim.x + threadIdx.x;
    if (t >= NN * HH) return;
    int n = t >> 7, c = t & 127;
    int b = batch[n];
    atomicAdd(&g_pool[b * HH + c], h[t]);
    if (c == 0) atomicAdd(&g_pcnt[b], 1.f);
}

__global__ void k_heads(const float* __restrict__ dw1, const float* __restrict__ db1,
                        const float* __restrict__ dw2, const float* __restrict__ db2,
                        const float* __restrict__ tw1, const float* __restrict__ tb1,
                        const float* __restrict__ tw2, const float* __restrict__ tb2,
                        float* __restrict__ out)
{
    const float* W1 = blockIdx.x ? tw1 : dw1;
    const float* B1 = blockIdx.x ? tb1 : db1;
    const float* W2 = blockIdx.x ? tw2 : dw2;
    const float* B2 = blockIdx.x ? tb2 : db2;

    __shared__ float hg[GG][HH];
    __shared__ float t1[GG][64];
    int t = threadIdx.x;

    for (int i = t; i < GG * HH; i += 256) {
        int g = i >> 7;
        hg[g][i & 127] = g_pool[i] / fmaxf(g_pcnt[g], 1.f);
    }
    __syncthreads();
    for (int i = t; i < GG * 64; i += 256) {
        int g = i >> 6, j = i & 63;
        float acc = B1[j];
        for (int c = 0; c < 128; c++) acc += hg[g][c] * W1[c * 64 + j];
        t1[g][j] = fmaxf(acc, 0.f);
    }
    __syncthreads();
    for (int i = t; i < GG * OO; i += 256) {
        int g = i / OO, o = i % OO;
        float acc = B2[o];
        for (int j = 0; j < 64; j++) acc += t1[g][j] * W2[j * OO + o];
        out[blockIdx.x * GG * OO + i] = acc;
    }
}

// ---------------- launch ----------------
extern "C" void kernel_launch(void* const* d_in, const int* in_sizes, int n_in,
                              void* d_out, int out_size)
{
    const float* x      = (const float*)d_in[0];
    const float* eattr  = (const float*)d_in[1];
    const float* node_w = (const float*)d_in[2];
    const float* node_b = (const float*)d_in[3];
    const float* edge_w = (const float*)d_in[4];
    const float* edge_b = (const float*)d_in[5];
    const float* Wq  = (const float*)d_in[6];
    const float* bq  = (const float*)d_in[7];
    const float* Wk  = (const float*)d_in[8];
    const float* bk  = (const float*)d_in[9];
    const float* Wv  = (const float*)d_in[10];
    const float* bv  = (const float*)d_in[11];
    const float* We  = (const float*)d_in[12];
    const float* Wsk = (const float*)d_in[13];
    const float* bsk = (const float*)d_in[14];
    const float* lng = (const float*)d_in[15];
    const float* lnb = (const float*)d_in[16];
    const float* dw1 = (const float*)d_in[17];
    const float* db1 = (const float*)d_in[18];
    const float* dw2 = (const float*)d_in[19];
    const float* db2 = (const float*)d_in[20];
    const float* tw1 = (const float*)d_in[21];
    const float* tb1 = (const float*)d_in[22];
    const float* tw2 = (const float*)d_in[23];
    const float* tb2 = (const float*)d_in[24];
    const int*   ei    = (const int*)d_in[25];
    const int*   batch = (const int*)d_in[26];
    float* out = (float*)d_out;

    float *hA, *hB, *qp, *kp, *vp, *sp;
    cudaGetSymbolAddress((void**)&hA, g_hA);
    cudaGetSymbolAddress((void**)&hB, g_hB);
    cudaGetSymbolAddress((void**)&qp, g_q);
    cudaGetSymbolAddress((void**)&kp, g_k);
    cudaGetSymbolAddress((void**)&vp, g_v);
    cudaGetSymbolAddress((void**)&sp, g_s);

    dim3 gg(NN / BM, 4);
    dim3 gp(NN / BM, 4);

    // gemm4 (layer 0) lands in the ncu-profiled slot (#4).
    k_zero<<<(NN + 255) / 256, 256>>>();
    k_prepWtu<<<(LL * 4 * 32 * HH + 255) / 256, 256>>>(We);
    k_nodeproj<<<(NN * HH + 255) / 256, 256>>>(x, node_w, node_b);
    gemm4<<<gg, 128>>>(hA, Wq, Wk, Wv, Wsk, bq, bk, bv, bsk, qp, kp, vp, sp);
    gemm_u<<<gp, 128>>>(qp, 0);
    k_hist<<<(EE + 255) / 256, 256>>>(ei);
    k_scan<<<1, 1024>>>();
    k_scatter<<<(EE + 255) / 256, 256>>>(ei);
    k_edgeproj<<<(EE * HH + 255) / 256, 256>>>(eattr, edge_w, edge_b);

    float* hcur = hA;
    float* hnxt = hB;
    for (int i = 0; i < LL; i++) {
        if (i > 0) {
            gemm4<<<gg, 128>>>(hcur,
                               Wq + i * HH * HH, Wk + i * HH * HH,
                               Wv + i * HH * HH, Wsk + i * HH * HH,
                               bq + i * HH, bk + i * HH, bv + i * HH, bsk + i * HH,
                               qp, kp, vp, sp);
            gemm_u<<<gp, 128>>>(qp, i);
        }
        k_attn2<<<(NN * 32) / 256, 256>>>(qp, kp, vp, sp);
        gemm_p<<<gp, 128>>>(We + i * HH * HH);
        k_lnrelu<<<(NN * 32) / 256, 256>>>(lng + i * HH, lnb + i * HH, hnxt);
        float* tmp = hcur; hcur = hnxt; hnxt = tmp;
    }

    k_pool<<<(NN * HH + 255) / 256, 256>>>(hcur, batch);
    k_heads<<<2, 256>>>(dw1, db1, dw2, db2, tw1, tb1, tw2, tb2, out);
}

// round 11
// speedup vs baseline: 2.2065x; 1.8062x over previous
#include <cuda_runtime.h>
#include <math.h>

#define NN 40000
#define EE 640000
#define GG 32
#define HH 128
#define LL 4
#define OO 100

// ---------------- device scratch ----------------
__device__ float g_hA[NN * HH];
__device__ float g_hB[NN * HH];
__device__ float g_q [NN * HH];
__device__ float g_k [NN * HH];
__device__ float g_v [NN * HH];
__device__ float g_s [NN * HH];
__device__ float g_eap[EE * 8];        // raw edge_attr, CSR-permuted, padded to 8
__device__ float g_z  [NN * 24];       // per node: 4 heads x (5 z + 1 zb)
__device__ float g_agg[NN * 24];       // per node: 4 heads x (5 aggea + 1 alpha-mass)
__device__ float g_tmpv[NN * HH];      // v-part + skip (pre-LN)
__device__ float g_Y  [LL * 4 * 5 * 32];
__device__ float g_yb [LL * 4 * 32];
__device__ float g_Z2 [LL * 5 * 128];
__device__ float g_zb2[LL * 128];
__device__ int   g_hist[NN];
__device__ int   g_rowstart[NN + 1];
__device__ int   g_cursor[NN];
__device__ int   g_edgepos[EE];
__device__ int   g_csrsrc[EE];
__device__ float g_pool[GG * HH];
__device__ float g_pcnt[GG];

// ---------------- CSR construction ----------------
__global__ void k_zero()
{
    int i = blockIdx.x * blockDim.x + threadIdx.x;
    if (i < NN) g_hist[i] = 0;
    if (i < GG * HH) g_pool[i] = 0.f;
    if (i < GG) g_pcnt[i] = 0.f;
}

__global__ void k_hist(const int* __restrict__ ei)
{
    int e = blockIdx.x * blockDim.x + threadIdx.x;
    if (e < EE) atomicAdd(&g_hist[ei[EE + e]], 1);
}

__global__ void k_scan()
{
    const int T = 1024, CH = 40;
    __shared__ int sh[T];
    int t = threadIdx.x;
    int base = t * CH;
    int loc[CH];
    int run = 0;
#pragma unroll
    for (int i = 0; i < CH; i++) {
        int idx = base + i;
        int vv = (idx < NN) ? g_hist[idx] : 0;
        loc[i] = run;
        run += vv;
    }
    sh[t] = run;
    __syncthreads();
    for (int off = 1; off < T; off <<= 1) {
        int vv = (t >= off) ? sh[t - off] : 0;
        __syncthreads();
        sh[t] += vv;
        __syncthreads();
    }
    int offset = (t > 0) ? sh[t - 1] : 0;
#pragma unroll
    for (int i = 0; i < CH; i++) {
        int idx = base + i;
        if (idx < NN) {
            int p = offset + loc[i];
            g_rowstart[idx] = p;
            g_cursor[idx]   = p;
        }
    }
    if (t == T - 1) g_rowstart[NN] = sh[T - 1];
}

__global__ void k_scatter(const int* __restrict__ ei)
{
    int e = blockIdx.x * blockDim.x + threadIdx.x;
    if (e < EE) {
        int dst = ei[EE + e];
        int pos = atomicAdd(&g_cursor[dst], 1);
        g_edgepos[e] = pos;
        g_csrsrc[pos] = ei[e];
    }
}

// permute raw edge_attr into CSR order (padded to 8 floats)
__global__ void k_permea(const float* __restrict__ ea)
{
    int e = blockIdx.x * blockDim.x + threadIdx.x;
    if (e >= EE) return;
    int pos = g_edgepos[e];
    float* dst = g_eap + (size_t)pos * 8;
    const float* src = ea + (size_t)e * 5;
    dst[0] = src[0]; dst[1] = src[1]; dst[2] = src[2];
    dst[3] = src[3]; dst[4] = src[4];
    dst[5] = 0.f; dst[6] = 0.f; dst[7] = 0.f;
}

// ---------------- input projection ----------------
__global__ void k_nodeproj(const float* __restrict__ x,
                           const float* __restrict__ w,
                           const float* __restrict__ b)
{
    int t = blockIdx.x * blockDim.x + threadIdx.x;
    if (t >= NN * HH) return;
    int n = t >> 7, c = t & 127;
    const float* xr = x + n * 4;
    float acc = b[c];
    acc += xr[0] * w[c] + xr[1] * w[128 + c] + xr[2] * w[256 + c] + xr[3] * w[384 + c];
    g_hA[t] = acc;
}

// ---------------- weight precompute: Y, yb, Z2, zb2 ----------------
__global__ void k_prep(const float* __restrict__ We,
                       const float* __restrict__ edge_w,
                       const float* __restrict__ edge_b)
{
    const float scale = 0.17677669529663687f;
    int t = blockIdx.x * blockDim.x + threadIdx.x;
    if (t < 2560) {                       // Y[l][h][m][c]
        int l = t / 640, r = t % 640;
        int h = r / 160, r2 = r % 160;
        int m = r2 / 32, c = r2 % 32;
        float acc = 0.f;
        for (int j = 0; j < 128; j++)
            acc += edge_w[m * 128 + j] * We[l * 16384 + j * 128 + h * 32 + c];
        g_Y[t] = acc * scale;
    } else if (t < 3072) {                // yb[l][h][c]
        int i = t - 2560;
        int l = i / 128, h = (i % 128) / 32, c = i % 32;
        float acc = 0.f;
        for (int j = 0; j < 128; j++)
            acc += edge_b[j] * We[l * 16384 + j * 128 + h * 32 + c];
        g_yb[i] = acc * scale;
    } else if (t < 5632) {                // Z2[l][m][col]
        int i = t - 3072;
        int l = i / 640, m = (i % 640) / 128, col = i % 128;
        float acc = 0.f;
        for (int j = 0; j < 128; j++)
            acc += edge_w[m * 128 + j] * We[l * 16384 + j * 128 + col];
        g_Z2[i] = acc;
    } else if (t < 6144) {                // zb2[l][col]
        int i = t - 5632;
        int l = i / 128, col = i % 128;
        float acc = 0.f;
        for (int j = 0; j < 128; j++)
            acc += edge_b[j] * We[l * 16384 + j * 128 + col];
        g_zb2[i] = acc;
    }
}

// ---------------- fused 4-matrix GEMM (proven) ----------------
#define BM 64
#define BK 16

__global__ void gemm4(const float* __restrict__ A,
                      const float* __restrict__ B0, const float* __restrict__ B1,
                      const float* __restrict__ B2, const float* __restrict__ B3,
                      const float* __restrict__ c0, const float* __restrict__ c1,
                      const float* __restrict__ c2, const float* __restrict__ c3,
                      float* __restrict__ C0, float* __restrict__ C1,
                      float* __restrict__ C2, float* __restrict__ C3)
{
    const float* B    = (blockIdx.y == 0) ? B0 : (blockIdx.y == 1) ? B1 : (blockIdx.y == 2) ? B2 : B3;
    const float* bias = (blockIdx.y == 0) ? c0 : (blockIdx.y == 1) ? c1 : (blockIdx.y == 2) ? c2 : c3;
    float* C          = (blockIdx.y == 0) ? C0 : (blockIdx.y == 1) ? C1 : (blockIdx.y == 2) ? C2 : C3;

    __shared__ float As[BK][BM + 4];
    __shared__ float Bs[BK][128];
    int tid  = threadIdx.x;
    int tcol = tid & 15;
    int trow = tid >> 4;
    int block_m = blockIdx.x * BM;

    float acc[8][8];
#pragma unroll
    for (int i = 0; i < 8; i++)
#pragma unroll
        for (int j = 0; j < 8; j++) acc[i][j] = 0.f;

    for (int k0 = 0; k0 < 128; k0 += BK) {
#pragma unroll
        for (int it = 0; it < 2; it++) {
            int f = tid + it * 128;
            int row = f >> 2;
            int kq  = f & 3;
            float4 a = *(const float4*)&A[(size_t)(block_m + row) * 128 + k0 + kq * 4];
            As[kq * 4 + 0][row] = a.x;
            As[kq * 4 + 1][row] = a.y;
            As[kq * 4 + 2][row] = a.z;
            As[kq * 4 + 3][row] = a.w;
        }
#pragma unroll
        for (int it = 0; it < 4; it++) {
            int f = tid + it * 128;
            int krow = f >> 5;
            int nq   = f & 31;
            *(float4*)&Bs[krow][nq * 4] = *(const float4*)&B[(k0 + krow) * 128 + nq * 4];
        }
        __syncthreads();
#pragma unroll
        for (int k = 0; k < BK; k++) {
            float a[8], b[8];
            *(float4*)&a[0] = *(float4*)&As[k][trow * 4];
            *(float4*)&a[4] = *(float4*)&As[k][32 + trow * 4];
            *(float4*)&b[0] = *(float4*)&Bs[k][tcol * 4];
            *(float4*)&b[4] = *(float4*)&Bs[k][64 + tcol * 4];
#pragma unroll
            for (int i = 0; i < 8; i++)
#pragma unroll
                for (int j = 0; j < 8; j++)
                    acc[i][j] += a[i] * b[j];
        }
        __syncthreads();
    }

    float4 bLo = *(const float4*)&bias[tcol * 4];
    float4 bHi = *(const float4*)&bias[64 + tcol * 4];
#pragma unroll
    for (int i = 0; i < 8; i++) {
        int row = block_m + ((i < 4) ? (trow * 4 + i) : (32 + trow * 4 + i - 4));
        float4 lo, hi;
        lo.x = acc[i][0] + bLo.x; lo.y = acc[i][1] + bLo.y;
        lo.z = acc[i][2] + bLo.z; lo.w = acc[i][3] + bLo.w;
        hi.x = acc[i][4] + bHi.x; hi.y = acc[i][5] + bHi.y;
        hi.z = acc[i][6] + bHi.z; hi.w = acc[i][7] + bHi.w;
        *(float4*)&C[(size_t)row * 128 + tcol * 4]      = lo;
        *(float4*)&C[(size_t)row * 128 + 64 + tcol * 4] = hi;
    }
}

// ---------------- z kernel: z[n,h,m]=q_h.Y[l,h,m], zb[n,h]=q_h.yb[l,h] ----------------
// one thread per (node, head)
__global__ void k_z(const float* __restrict__ q, int l)
{
    int t = blockIdx.x * blockDim.x + threadIdx.x;
    if (t >= NN * 4) return;
    int n = t >> 2, h = t & 3;
    const float* qr  = q + (size_t)n * 128 + h * 32;
    const float* Yh  = g_Y  + (size_t)(l * 4 + h) * 160;
    const float* ybh = g_yb + (size_t)(l * 4 + h) * 32;
    float a0 = 0.f, a1 = 0.f, a2 = 0.f, a3 = 0.f, a4 = 0.f, a5 = 0.f;
#pragma unroll 8
    for (int c = 0; c < 32; c++) {
        float qv = qr[c];
        a0 += qv * Yh[c];
        a1 += qv * Yh[32 + c];
        a2 += qv * Yh[64 + c];
        a3 += qv * Yh[96 + c];
        a4 += qv * Yh[128 + c];
        a5 += qv * ybh[c];
    }
    float* zo = g_z + (size_t)n * 24 + h * 6;
    zo[0] = a0; zo[1] = a1; zo[2] = a2; zo[3] = a3; zo[4] = a4; zo[5] = a5;
}

// ---------------- attention v5: group-per-head, 5-dim edge features ----------------
// warp per node; group g (8 lanes) owns head g. Per edge: k,v gather (own head
// chunk) + broadcast 5-dim raw edge_attr; logit reduction = 3 intra-group shuffles.
__global__ void k_attn5(const float* __restrict__ q, const float* __restrict__ kk,
                        const float* __restrict__ vv, const float* __restrict__ sk)
{
    int wrp  = (blockIdx.x * blockDim.x + threadIdx.x) >> 5;
    int lane = threadIdx.x & 31;
    if (wrp >= NN) return;
    int g  = lane >> 3;
    int l8 = lane & 7;
    const float scale = 0.17677669529663687f;
    const unsigned FULL = 0xffffffffu;

    // own head's q chunk, pre-scaled
    float4 q4 = *(const float4*)(q + (size_t)wrp * 128 + g * 32 + l8 * 4);
    q4.x *= scale; q4.y *= scale; q4.z *= scale; q4.w *= scale;

    // own head's z (5) + zb (1)
    const float* zp = g_z + (size_t)wrp * 24 + g * 6;
    float z0 = zp[0], z1 = zp[1], z2 = zp[2], z3 = zp[3], z4 = zp[4], zb = zp[5];

    float ssum = 0.f;
    float ag0 = 0.f, ag1 = 0.f, ag2 = 0.f, ag3 = 0.f, ag4 = 0.f;
    float4 vacc = make_float4(0.f, 0.f, 0.f, 0.f);

    int beg = g_rowstart[wrp], end = g_rowstart[wrp + 1];
    int idx = beg;

    for (; idx + 1 < end; idx += 2) {
        int sA = g_csrsrc[idx];
        int sB = g_csrsrc[idx + 1];
        float4 eaA  = *(const float4*)(g_eap + (size_t)idx * 8);
        float  eaA4 = g_eap[(size_t)idx * 8 + 4];
        float4 eaB  = *(const float4*)(g_eap + (size_t)(idx + 1) * 8);
        float  eaB4 = g_eap[(size_t)(idx + 1) * 8 + 4];
        float4 kA = *(const float4*)(kk + (size_t)sA * 128 + g * 32 + l8 * 4);
        float4 kB = *(const float4*)(kk + (size_t)sB * 128 + g * 32 + l8 * 4);
        float4 vA = *(const float4*)(vv + (size_t)sA * 128 + g * 32 + l8 * 4);
        float4 vB = *(const float4*)(vv + (size_t)sB * 128 + g * 32 + l8 * 4);

        float pA = q4.x * kA.x + q4.y * kA.y + q4.z * kA.z + q4.w * kA.w;
        float pB = q4.x * kB.x + q4.y * kB.y + q4.z * kB.z + q4.w * kB.w;
        pA += __shfl_xor_sync(FULL, pA, 1);  pB += __shfl_xor_sync(FULL, pB, 1);
        pA += __shfl_xor_sync(FULL, pA, 2);  pB += __shfl_xor_sync(FULL, pB, 2);
        pA += __shfl_xor_sync(FULL, pA, 4);  pB += __shfl_xor_sync(FULL, pB, 4);

        float dA = zb + eaA.x * z0 + eaA.y * z1 + eaA.z * z2 + eaA.w * z3 + eaA4 * z4;
        float dB = zb + eaB.x * z0 + eaB.y * z1 + eaB.z * z2 + eaB.w * z3 + eaB4 * z4;

        float wA = __expf(pA + dA);
        float wB = __expf(pB + dB);
        ssum += wA + wB;

        ag0 += wA * eaA.x + wB * eaB.x;
        ag1 += wA * eaA.y + wB * eaB.y;
        ag2 += wA * eaA.z + wB * eaB.z;
        ag3 += wA * eaA.w + wB * eaB.w;
        ag4 += wA * eaA4  + wB * eaB4;

        vacc.x += wA * vA.x + wB * vB.x;
        vacc.y += wA * vA.y + wB * vB.y;
        vacc.z += wA * vA.z + wB * vB.z;
        vacc.w += wA * vA.w + wB * vB.w;
    }

    if (idx < end) {
        int sA = g_csrsrc[idx];
        float4 eaA  = *(const float4*)(g_eap + (size_t)idx * 8);
        float  eaA4 = g_eap[(size_t)idx * 8 + 4];
        float4 kA = *(const float4*)(kk + (size_t)sA * 128 + g * 32 + l8 * 4);
        float4 vA = *(const float4*)(vv + (size_t)sA * 128 + g * 32 + l8 * 4);

        float pA = q4.x * kA.x + q4.y * kA.y + q4.z * kA.z + q4.w * kA.w;
        pA += __shfl_xor_sync(FULL, pA, 1);
        pA += __shfl_xor_sync(FULL, pA, 2);
        pA += __shfl_xor_sync(FULL, pA, 4);

        float dA = zb + eaA.x * z0 + eaA.y * z1 + eaA.z * z2 + eaA.w * z3 + eaA4 * z4;
        float wA = __expf(pA + dA);
        ssum += wA;
        ag0 += wA * eaA.x; ag1 += wA * eaA.y; ag2 += wA * eaA.z;
        ag3 += wA * eaA.w; ag4 += wA * eaA4;
        vacc.x += wA * vA.x; vacc.y += wA * vA.y;
        vacc.z += wA * vA.z; vacc.w += wA * vA.w;
    }

    float inv = 1.f / (ssum + 1e-16f);

    float4 s4 = *(const float4*)(sk + (size_t)wrp * 128 + lane * 4);
    float4 t;
    t.x = vacc.x * inv + s4.x;
    t.y = vacc.y * inv + s4.y;
    t.z = vacc.z * inv + s4.z;
    t.w = vacc.w * inv + s4.w;
    *(float4*)(g_tmpv + (size_t)wrp * 128 + lane * 4) = t;

    if (l8 == 0) {
        float* ao = g_agg + (size_t)wrp * 24 + g * 6;
        ao[0] = ag0 * inv;
        ao[1] = ag1 * inv;
        ao[2] = ag2 * inv;
        ao[3] = ag3 * inv;
        ao[4] = ag4 * inv;
        ao[5] = ssum * inv;    // alpha-mass: 1 if edges exist, 0 if not
    }
}

// ---------------- fused og + LN + ReLU ----------------
// og[ch] = sum_m aggea[n, h(ch), m] * Z2[m, ch] + mass * zb2[ch]; out = relu(LN(tmpv+og))
__global__ void k_oglnrelu(const float* __restrict__ lng, const float* __restrict__ lnb,
                           int l, float* __restrict__ hout)
{
    int wrp  = (blockIdx.x * blockDim.x + threadIdx.x) >> 5;
    int lane = threadIdx.x & 31;
    if (wrp >= NN) return;
    int g = lane >> 3;

    const float* ap = g_agg + (size_t)wrp * 24 + g * 6;
    float a0 = ap[0], a1 = ap[1], a2 = ap[2], a3 = ap[3], a4 = ap[4], mass = ap[5];

    const float* Z2l  = g_Z2  + (size_t)l * 640;
    const float* zb2l = g_zb2 + (size_t)l * 128;
    float4 w0 = *(const float4*)&Z2l[  0 + lane * 4];
    float4 w1 = *(const float4*)&Z2l[128 + lane * 4];
    float4 w2 = *(const float4*)&Z2l[256 + lane * 4];
    float4 w3 = *(const float4*)&Z2l[384 + lane * 4];
    float4 w4 = *(const float4*)&Z2l[512 + lane * 4];
    float4 zb = *(const float4*)&zb2l[lane * 4];

    float4 t = *(const float4*)(g_tmpv + (size_t)wrp * 128 + lane * 4);
    float ox = t.x + a0 * w0.x + a1 * w1.x + a2 * w2.x + a3 * w3.x + a4 * w4.x + mass * zb.x;
    float oy = t.y + a0 * w0.y + a1 * w1.y + a2 * w2.y + a3 * w3.y + a4 * w4.y + mass * zb.y;
    float oz = t.z + a0 * w0.z + a1 * w1.z + a2 * w2.z + a3 * w3.z + a4 * w4.z + mass * zb.z;
    float ow = t.w + a0 * w0.w + a1 * w1.w + a2 * w2.w + a3 * w3.w + a4 * w4.w + mass * zb.w;

    float s = ox + oy + oz + ow;
#pragma unroll
    for (int off = 16; off; off >>= 1) s += __shfl_xor_sync(0xffffffffu, s, off);
    float mu = s * 0.0078125f;
    float dx = ox - mu, dy = oy - mu, dz = oz - mu, dw = ow - mu;
    float sq = dx * dx + dy * dy + dz * dz + dw * dw;
#pragma unroll
    for (int off = 16; off; off >>= 1) sq += __shfl_xor_sync(0xffffffffu, sq, off);
    float r = rsqrtf(sq * 0.0078125f + 1e-5f);

    float4 g4 = *(const float4*)&lng[lane * 4];
    float4 b4 = *(const float4*)&lnb[lane * 4];
    float4 res;
    res.x = fmaxf(0.f, dx * r * g4.x + b4.x);
    res.y = fmaxf(0.f, dy * r * g4.y + b4.y);
    res.z = fmaxf(0.f, dz * r * g4.z + b4.z);
    res.w = fmaxf(0.f, dw * r * g4.w + b4.w);
    *(float4*)(hout + (size_t)wrp * 128 + lane * 4) = res;
}

// ---------------- global mean pool + MLP heads ----------------
__global__ void k_pool(const float* __restrict__ h, const int* __restrict__ batch)
{
    int t = blockIdx.x * blockDim.x + threadIdx.x;
    if (t >= NN * HH) return;
    int n = t >> 7, c = t & 127;
    int b = batch[n];
    atomicAdd(&g_pool[b * HH + c], h[t]);
    if (c == 0) atomicAdd(&g_pcnt[b], 1.f);
}

__global__ void k_heads(const float* __restrict__ dw1, const float* __restrict__ db1,
                        const float* __restrict__ dw2, const float* __restrict__ db2,
                        const float* __restrict__ tw1, const float* __restrict__ tb1,
                        const float* __restrict__ tw2, const float* __restrict__ tb2,
                        float* __restrict__ out)
{
    const float* W1 = blockIdx.x ? tw1 : dw1;
    const float* B1 = blockIdx.x ? tb1 : db1;
    const float* W2 = blockIdx.x ? tw2 : dw2;
    const float* B2 = blockIdx.x ? tb2 : db2;

    __shared__ float hg[GG][HH];
    __shared__ float t1[GG][64];
    int t = threadIdx.x;

    for (int i = t; i < GG * HH; i += 256) {
        int g = i >> 7;
        hg[g][i & 127] = g_pool[i] / fmaxf(g_pcnt[g], 1.f);
    }
    __syncthreads();
    for (int i = t; i < GG * 64; i += 256) {
        int g = i >> 6, j = i & 63;
        float acc = B1[j];
        for (int c = 0; c < 128; c++) acc += hg[g][c] * W1[c * 64 + j];
        t1[g][j] = fmaxf(acc, 0.f);
    }
    __syncthreads();
    for (int i = t; i < GG * OO; i += 256) {
        int g = i / OO, o = i % OO;
        float acc = B2[o];
        for (int j = 0; j < 64; j++) acc += t1[g][j] * W2[j * OO + o];
        out[blockIdx.x * GG * OO + i] = acc;
    }
}

// ---------------- launch ----------------
extern "C" void kernel_launch(void* const* d_in, const int* in_sizes, int n_in,
                              void* d_out, int out_size)
{
    const float* x      = (const float*)d_in[0];
    const float* eattr  = (const float*)d_in[1];
    const float* node_w = (const float*)d_in[2];
    const float* node_b = (const float*)d_in[3];
    const float* edge_w = (const float*)d_in[4];
    const float* edge_b = (const float*)d_in[5];
    const float* Wq  = (const float*)d_in[6];
    const float* bq  = (const float*)d_in[7];
    const float* Wk  = (const float*)d_in[8];
    const float* bk  = (const float*)d_in[9];
    const float* Wv  = (const float*)d_in[10];
    const float* bv  = (const float*)d_in[11];
    const float* We  = (const float*)d_in[12];
    const float* Wsk = (const float*)d_in[13];
    const float* bsk = (const float*)d_in[14];
    const float* lng = (const float*)d_in[15];
    const float* lnb = (const float*)d_in[16];
    const float* dw1 = (const float*)d_in[17];
    const float* db1 = (const float*)d_in[18];
    const float* dw2 = (const float*)d_in[19];
    const float* db2 = (const float*)d_in[20];
    const float* tw1 = (const float*)d_in[21];
    const float* tb1 = (const float*)d_in[22];
    const float* tw2 = (const float*)d_in[23];
    const float* tb2 = (const float*)d_in[24];
    const int*   ei    = (const int*)d_in[25];
    const int*   batch = (const int*)d_in[26];
    float* out = (float*)d_out;

    float *hA, *hB, *qp, *kp, *vp, *sp;
    cudaGetSymbolAddress((void**)&hA, g_hA);
    cudaGetSymbolAddress((void**)&hB, g_hB);
    cudaGetSymbolAddress((void**)&qp, g_q);
    cudaGetSymbolAddress((void**)&kp, g_k);
    cudaGetSymbolAddress((void**)&vp, g_v);
    cudaGetSymbolAddress((void**)&sp, g_s);

    dim3 gg(NN / BM, 4);

    // gemm4 (layer 0) stays in the ncu-profiled slot (#4).
    k_zero<<<(NN + 255) / 256, 256>>>();
    k_hist<<<(EE + 255) / 256, 256>>>(ei);
    k_nodeproj<<<(NN * HH + 255) / 256, 256>>>(x, node_w, node_b);
    gemm4<<<gg, 128>>>(hA, Wq, Wk, Wv, Wsk, bq, bk, bv, bsk, qp, kp, vp, sp);
    k_scan<<<1, 1024>>>();
    k_scatter<<<(EE + 255) / 256, 256>>>(ei);
    k_permea<<<(EE + 255) / 256, 256>>>(eattr);
    k_prep<<<24, 256>>>(We, edge_w, edge_b);
    k_z<<<(NN * 4 + 255) / 256, 256>>>(qp, 0);

    float* hcur = hA;
    float* hnxt = hB;
    for (int i = 0; i < LL; i++) {
        if (i > 0) {
            gemm4<<<gg, 128>>>(hcur,
                               Wq + i * HH * HH, Wk + i * HH * HH,
                               Wv + i * HH * HH, Wsk + i * HH * HH,
                               bq + i * HH, bk + i * HH, bv + i * HH, bsk + i * HH,
                               qp, kp, vp, sp);
            k_z<<<(NN * 4 + 255) / 256, 256>>>(qp, i);
        }
        k_attn5<<<(NN * 32) / 256, 256>>>(qp, kp, vp, sp);
        k_oglnrelu<<<(NN * 32) / 256, 256>>>(lng + i * HH, lnb + i * HH, i, hnxt);
        float* tmp = hcur; hcur = hnxt; hnxt = tmp;
    }

    k_pool<<<(NN * HH + 255) / 256, 256>>>(hcur, batch);
    k_heads<<<2, 256>>>(dw1, db1, dw2, db2, tw1, tb1, tw2, tb2, out);
}